// round 4
// baseline (speedup 1.0000x reference)
#include <cuda_runtime.h>
#include <cstdint>

#define NODES 50000
#define EDGES 800000
#define HID   128
#define NLAYER 3

// ---------------- scratch (static device globals; no allocation) ----------------
__device__ float    g_x   [NODES * HID];       // fp32 node state (readout + reference)
__device__ uint32_t g_x32 [NODES * HID];       // tf32-bit shadow (GEMM A input)
__device__ float    g_pq  [NODES * 2 * HID];   // [P | Q] per node (k_aggr input)
__device__ uint32_t g_H32 [NODES * HID];       // segment_sum(relu_h), tf32 bits
__device__ uint32_t g_ag32[NODES * HID];       // aggr, tf32 bits
__device__ uint32_t g_t32 [NODES * HID];       // update hidden, tf32 bits
__device__ int   g_esrc[EDGES];
__device__ float g_eea [EDGES];
__device__ int   g_deg [NODES];
__device__ int   g_tmp [NODES];
__device__ int   g_rowptr[NODES + 1];
__device__ int   g_cursor[NODES];
__device__ float g_invdeg[NODES];
__device__ float g_gate  [NODES];
__device__ uint32_t g_wT[6 * HID * HID];       // 6 transposed weights, tf32 bits
__device__ float g_gvec[HID];
__device__ int   g_is64;
__device__ int   g_bsum[64];
__device__ int   g_boff[64];

// ================= helpers =================
__device__ __forceinline__ uint32_t cvt_tf32(float x) {
    uint32_t r;
    asm("cvt.rna.tf32.f32 %0, %1;" : "=r"(r) : "f"(x));
    return r;
}
__device__ __forceinline__ void mma8(float* c, const uint32_t* a, const uint32_t* b) {
    asm volatile(
        "mma.sync.aligned.m16n8k8.row.col.f32.tf32.tf32.f32 "
        "{%0,%1,%2,%3},{%4,%5,%6,%7},{%8,%9},{%0,%1,%2,%3};"
        : "+f"(c[0]), "+f"(c[1]), "+f"(c[2]), "+f"(c[3])
        : "r"(a[0]), "r"(a[1]), "r"(a[2]), "r"(a[3]), "r"(b[0]), "r"(b[1]));
}
__device__ __forceinline__ void cp16(uint32_t dst, const void* src, int nbytes) {
    asm volatile("cp.async.cg.shared.global [%0], [%1], 16, %2;"
                 :: "r"(dst), "l"(src), "r"(nbytes));
}

// ================= CSR build =================
__global__ void k_detect(const int* __restrict__ ei) {
    if (blockIdx.x == 0 && threadIdx.x == 0) {
        int z = 1;
        #pragma unroll
        for (int i = 1; i < 16; i += 2) if (ei[i] != 0) z = 0;
        g_is64 = z;
    }
}
__global__ void k_zero_deg(int N) {
    int i = blockIdx.x * blockDim.x + threadIdx.x;
    if (i < N) g_deg[i] = 0;
}
__global__ void k_count(const int* __restrict__ ei, int E) {
    int e = blockIdx.x * blockDim.x + threadIdx.x;
    if (e >= E) return;
    int is64 = g_is64;
    int dst = is64 ? ei[2 * E + 2 * e] : ei[E + e];
    atomicAdd(&g_deg[dst], 1);
}
__global__ void k_scan1(int N) {
    __shared__ int s[1024];
    int tid = threadIdx.x;
    int i = blockIdx.x * 1024 + tid;
    int v = (i < N) ? g_deg[i] : 0;
    s[tid] = v;
    __syncthreads();
    for (int off = 1; off < 1024; off <<= 1) {
        int t = (tid >= off) ? s[tid - off] : 0;
        __syncthreads();
        s[tid] += t;
        __syncthreads();
    }
    if (i < N) g_tmp[i] = s[tid];
    if (tid == 1023) g_bsum[blockIdx.x] = s[1023];
}
__global__ void k_scan2(int nb) {
    __shared__ int s[64];
    int tid = threadIdx.x;
    int v = (tid < nb) ? g_bsum[tid] : 0;
    s[tid] = v;
    __syncthreads();
    for (int off = 1; off < 64; off <<= 1) {
        int t = (tid >= off) ? s[tid - off] : 0;
        __syncthreads();
        s[tid] += t;
        __syncthreads();
    }
    g_boff[tid] = s[tid] - v;   // exclusive
}
__global__ void k_scan3(int N) {
    int i = blockIdx.x * blockDim.x + threadIdx.x;
    if (i >= N) return;
    int incl = g_tmp[i] + g_boff[i >> 10];
    int d = g_deg[i];
    int excl = incl - d;
    g_rowptr[i] = excl;
    g_cursor[i] = excl;
    g_invdeg[i] = 1.0f / fmaxf((float)d, 1.0f);
    g_gate[i]   = (d > 0) ? 1.0f : 0.0f;
    if (i == N - 1) g_rowptr[N] = incl;
}
__global__ void k_scatter(const int* __restrict__ ei, const float* __restrict__ ea, int E) {
    int e = blockIdx.x * blockDim.x + threadIdx.x;
    if (e >= E) return;
    int is64 = g_is64;
    int src = is64 ? ei[2 * e]         : ei[e];
    int dst = is64 ? ei[2 * E + 2 * e] : ei[E + e];
    int pos = atomicAdd(&g_cursor[dst], 1);
    g_esrc[pos] = src;
    g_eea[pos]  = ea[e];
}

// ================= encoder =================
__global__ void k_encode(const float* __restrict__ nf, const float* __restrict__ W,
                         const float* __restrict__ b, int N) {
    int t = blockIdx.x * blockDim.x + threadIdx.x;
    if (t >= N * HID) return;
    int n = t >> 7, c = t & 127;
    float acc = b[c];
    #pragma unroll
    for (int k = 0; k < 5; k++) acc = fmaf(nf[n * 5 + k], W[k * HID + c], acc);
    g_x[t]   = acc;
    g_x32[t] = cvt_tf32(acc);
}

// ================= per-layer weight transpose repack (to tf32 bits) =================
__global__ void k_repackT(const float* __restrict__ W1, const float* __restrict__ W2,
                          const float* __restrict__ U1, const float* __restrict__ U2) {
    int t = blockIdx.x * blockDim.x + threadIdx.x;   // < 6*16384
    int w = t >> 14;
    int j = (t >> 7) & 127;
    int k = t & 127;
    float v;
    switch (w) {
        case 0:  v = W1[k * 128 + j];          break;
        case 1:  v = W1[(128 + k) * 128 + j];  break;
        case 2:  v = W2[k * 128 + j];          break;
        case 3:  v = U1[k * 128 + j];          break;
        case 4:  v = U1[(128 + k) * 128 + j];  break;
        default: v = U2[k * 128 + j];          break;
    }
    g_wT[t] = cvt_tf32(v);
}

// ================= tf32 mma.sync GEMM, cp.async double-buffered =================
// CTA tile 128x128, 8 warps (2m x 4n), warp tile 64x32, mma m16n8k8.
// K streamed as NCHUNK chunks of 32 (NCHUNK=8 => dual-input K=256 concat GEMM).
// Inputs are pre-converted tf32 bits. Chunk smem stride 36 words (conflict-free).
#define SMS 36
#define CHUNK_W (128 * SMS)                 // words per chunk buffer (4608)
#define GEMM_SMEM_BYTES (4 * CHUNK_W * 4)   // 73728

template<int NCHUNK, bool DUAL, bool BIAS, bool RELU, bool SCALE, bool LN, bool WF, bool W32>
__global__ void __launch_bounds__(256, 2)
gemm_mma(const uint32_t* __restrict__ A1, const uint32_t* __restrict__ A2,
         const uint32_t* __restrict__ B1, const uint32_t* __restrict__ B2,
         const float* __restrict__ bias,
         const float* __restrict__ rowscale, const float* __restrict__ rowgate,
         const float* __restrict__ lng, const float* __restrict__ lnb,
         float* __restrict__ Cf, uint32_t* __restrict__ C32, int M, int NO)
{
    extern __shared__ uint32_t sm[];
    const uint32_t smb = (uint32_t)__cvta_generic_to_shared(sm);

    const int tid = threadIdx.x;
    const int wid = tid >> 5, lane = tid & 31;
    const int g = lane >> 2, tig = lane & 3;
    const int warp_m = wid >> 2, warp_n = wid & 3;
    const int mw = warp_m * 64, nw = warp_n * 32;
    const int m0 = blockIdx.x * 128;

    float acc[4][4][4];
    #pragma unroll
    for (int i = 0; i < 4; i++)
        #pragma unroll
        for (int j = 0; j < 4; j++)
            #pragma unroll
            for (int r = 0; r < 4; r++) acc[i][j][r] = 0.0f;

    // per-thread copy coords (4 float4 each for A and B per chunk)
    const int crow = tid >> 1;              // 0..127  (2 threads per row, 4 float4 each)
    const int cq0  = (tid & 1) * 4;         // 0 or 4

    auto load_chunk = [&](int c, int buf) {
        const uint32_t* As_;
        const uint32_t* Bs_;
        int col;
        if (DUAL && c >= NCHUNK / 2) {
            As_ = A2; Bs_ = B2; col = (c - NCHUNK / 2) * 32;
        } else {
            As_ = A1; Bs_ = B1; col = c * 32;
        }
        uint32_t aBase = smb + (uint32_t)(buf * CHUNK_W) * 4u;
        uint32_t bBase = smb + (uint32_t)((2 + buf) * CHUNK_W) * 4u;
        int gr = m0 + crow;
        int ok = (gr < M) ? 16 : 0;
        const uint32_t* asrc = As_ + (size_t)(gr < M ? gr : 0) * 128 + col;
        const uint32_t* bsrc = Bs_ + (size_t)crow * 128 + col;
        #pragma unroll
        for (int u = 0; u < 4; u++) {
            int q = cq0 + ((u < 2) ? u : u + 2);   // q in {0,1,4,5} / {2,3,6,7} pattern
            // simpler: q covers {cq0, cq0+1, cq0+2, cq0+3}? need 8 float4 per row by 2 threads
            q = cq0 + u;                            // 0..3 or 4..7
            cp16(aBase + (uint32_t)(crow * SMS + q * 4) * 4u, asrc + q * 4, ok);
            cp16(bBase + (uint32_t)(crow * SMS + q * 4) * 4u, bsrc + q * 4, 16);
        }
    };

    load_chunk(0, 0);
    asm volatile("cp.async.commit_group;" ::: "memory");

    #pragma unroll
    for (int c = 0; c < NCHUNK; c++) {
        if (c + 1 < NCHUNK) {
            load_chunk(c + 1, (c + 1) & 1);
            asm volatile("cp.async.commit_group;" ::: "memory");
            asm volatile("cp.async.wait_group 1;" ::: "memory");
        } else {
            asm volatile("cp.async.wait_group 0;" ::: "memory");
        }
        __syncthreads();
        const uint32_t* As = sm + (c & 1) * CHUNK_W;
        const uint32_t* Bs = sm + (2 + (c & 1)) * CHUNK_W;
        #pragma unroll
        for (int ks = 0; ks < 4; ks++) {
            const int k0 = ks * 8;
            uint32_t af[4][4], bf[4][2];
            #pragma unroll
            for (int i = 0; i < 4; i++) {
                const uint32_t* base = &As[(mw + i * 16 + g) * SMS + k0 + tig];
                af[i][0] = base[0];
                af[i][1] = base[8 * SMS];
                af[i][2] = base[4];
                af[i][3] = base[8 * SMS + 4];
            }
            #pragma unroll
            for (int j = 0; j < 4; j++) {
                const uint32_t* base = &Bs[(nw + j * 8 + g) * SMS + k0 + tig];
                bf[j][0] = base[0];
                bf[j][1] = base[4];
            }
            #pragma unroll
            for (int i = 0; i < 4; i++)
                #pragma unroll
                for (int j = 0; j < 4; j++)
                    mma8(acc[i][j], af[i], bf[j]);
        }
        __syncthreads();
    }

    // ---------------- epilogue ----------------
    float bcol[4][2];
    #pragma unroll
    for (int j = 0; j < 4; j++) {
        int col = nw + j * 8 + 2 * tig;
        bcol[j][0] = (BIAS || SCALE) ? bias[col]     : 0.0f;
        bcol[j][1] = (BIAS || SCALE) ? bias[col + 1] : 0.0f;
    }

    if constexpr (LN) {
        float* sS  = (float*)sm;            // [128][4]
        float* sS2 = (float*)(sm + 512);
        float gcol[4][2], lcol[4][2];
        #pragma unroll
        for (int j = 0; j < 4; j++) {
            int col = nw + j * 8 + 2 * tig;
            gcol[j][0] = lng[col];     gcol[j][1] = lng[col + 1];
            lcol[j][0] = lnb[col];     lcol[j][1] = lnb[col + 1];
        }
        #pragma unroll
        for (int i = 0; i < 4; i++) {
            #pragma unroll
            for (int h = 0; h < 2; h++) {
                float s = 0.f, s2 = 0.f;
                #pragma unroll
                for (int j = 0; j < 4; j++) {
                    #pragma unroll
                    for (int r = 0; r < 2; r++) {
                        float v = acc[i][j][2 * h + r] + bcol[j][r];
                        s += v; s2 += v * v;
                    }
                }
                s  += __shfl_xor_sync(0xffffffffu, s, 1);
                s  += __shfl_xor_sync(0xffffffffu, s, 2);
                s2 += __shfl_xor_sync(0xffffffffu, s2, 1);
                s2 += __shfl_xor_sync(0xffffffffu, s2, 2);
                if (tig == 0) {
                    int rl = mw + i * 16 + g + 8 * h;
                    sS [rl * 4 + warp_n] = s;
                    sS2[rl * 4 + warp_n] = s2;
                }
            }
        }
        __syncthreads();
        #pragma unroll
        for (int i = 0; i < 4; i++) {
            #pragma unroll
            for (int h = 0; h < 2; h++) {
                int rl = mw + i * 16 + g + 8 * h;
                int row = m0 + rl;
                float s  = sS [rl * 4] + sS [rl * 4 + 1] + sS [rl * 4 + 2] + sS [rl * 4 + 3];
                float s2 = sS2[rl * 4] + sS2[rl * 4 + 1] + sS2[rl * 4 + 2] + sS2[rl * 4 + 3];
                float mu   = s * (1.0f / 128.0f);
                float var  = s2 * (1.0f / 128.0f) - mu * mu;
                float rstd = rsqrtf(var + 1e-5f);
                if (row < M) {
                    #pragma unroll
                    for (int j = 0; j < 4; j++) {
                        int col = nw + j * 8 + 2 * tig;
                        float v0 = fmaxf((acc[i][j][2*h]   + bcol[j][0] - mu) * rstd * gcol[j][0] + lcol[j][0], 0.f);
                        float v1 = fmaxf((acc[i][j][2*h+1] + bcol[j][1] - mu) * rstd * gcol[j][1] + lcol[j][1], 0.f);
                        if (WF) {
                            float2 o; o.x = v0; o.y = v1;
                            *(float2*)&Cf[(size_t)row * NO + col] = o;
                        }
                        if (W32) {
                            uint2 u; u.x = cvt_tf32(v0); u.y = cvt_tf32(v1);
                            *(uint2*)&C32[(size_t)row * NO + col] = u;
                        }
                    }
                }
            }
        }
    } else {
        #pragma unroll
        for (int i = 0; i < 4; i++) {
            #pragma unroll
            for (int h = 0; h < 2; h++) {
                int row = m0 + mw + i * 16 + g + 8 * h;
                if (row >= M) continue;
                float rs = 1.f, gt = 1.f;
                if (SCALE) { rs = rowscale[row]; gt = rowgate[row]; }
                #pragma unroll
                for (int j = 0; j < 4; j++) {
                    int col = nw + j * 8 + 2 * tig;
                    float v0 = acc[i][j][2 * h];
                    float v1 = acc[i][j][2 * h + 1];
                    if (SCALE) {
                        v0 = v0 * rs + gt * bcol[j][0];
                        v1 = v1 * rs + gt * bcol[j][1];
                    } else if (BIAS) {
                        v0 += bcol[j][0];
                        v1 += bcol[j][1];
                    }
                    if (RELU) { v0 = fmaxf(v0, 0.f); v1 = fmaxf(v1, 0.f); }
                    if (WF) {
                        float2 o; o.x = v0; o.y = v1;
                        *(float2*)&Cf[(size_t)row * NO + col] = o;
                    }
                    if (W32) {
                        uint2 u; u.x = cvt_tf32(v0); u.y = cvt_tf32(v1);
                        *(uint2*)&C32[(size_t)row * NO + col] = u;
                    }
                }
            }
        }
    }
}

// ================= edge aggregation: warp per node =================
__global__ void __launch_bounds__(256) k_aggr(const float* __restrict__ w1c, int N) {
    int warp = (blockIdx.x * blockDim.x + threadIdx.x) >> 5;
    int lane = threadIdx.x & 31;
    if (warp >= N) return;
    int node = warp;
    float4 p = *(const float4*)&g_pq[(size_t)node * 256 + lane * 4];
    float4 w = *(const float4*)&w1c[lane * 4];
    float4 acc = make_float4(0.f, 0.f, 0.f, 0.f);
    int s0 = g_rowptr[node], s1 = g_rowptr[node + 1];
    for (int j = s0; j < s1; j++) {
        int src  = g_esrc[j];
        float ea = g_eea[j];
        float4 q = *(const float4*)&g_pq[(size_t)src * 256 + 128 + lane * 4];
        acc.x += fmaxf(fmaf(ea, w.x, p.x + q.x), 0.0f);
        acc.y += fmaxf(fmaf(ea, w.y, p.y + q.y), 0.0f);
        acc.z += fmaxf(fmaf(ea, w.z, p.z + q.z), 0.0f);
        acc.w += fmaxf(fmaf(ea, w.w, p.w + q.w), 0.0f);
    }
    uint4 u;
    u.x = cvt_tf32(acc.x); u.y = cvt_tf32(acc.y);
    u.z = cvt_tf32(acc.z); u.w = cvt_tf32(acc.w);
    *(uint4*)&g_H32[(size_t)node * 128 + lane * 4] = u;
}

// ================= readout =================
__global__ void k_zero_gvec() { if (threadIdx.x < 128) g_gvec[threadIdx.x] = 0.0f; }
__global__ void k_mean(int N) {
    int c = threadIdx.x;
    int rows_per = (N + gridDim.x - 1) / gridDim.x;
    int r0 = blockIdx.x * rows_per;
    int r1 = min(r0 + rows_per, N);
    float s = 0.0f;
    for (int r = r0; r < r1; r++) s += g_x[(size_t)r * 128 + c];
    atomicAdd(&g_gvec[c], s);
}
__global__ void k_out(const float* __restrict__ W1, const float* __restrict__ b1,
                      const float* __restrict__ W2, const float* __restrict__ b2,
                      float* __restrict__ out, float invN) {
    __shared__ float gs[128];
    __shared__ float hs[128];
    int c = threadIdx.x;
    gs[c] = g_gvec[c] * invN;
    __syncthreads();
    float a = b1[c];
    #pragma unroll 8
    for (int k = 0; k < 128; k++) a = fmaf(gs[k], W1[k * 128 + c], a);
    hs[c] = fmaxf(a, 0.0f);
    __syncthreads();
    float o = b2[c];
    #pragma unroll 8
    for (int k = 0; k < 128; k++) o = fmaf(hs[k], W2[k * 128 + c], o);
    out[c] = o;
}

// ================= launch =================
extern "C" void kernel_launch(void* const* d_in, const int* in_sizes, int n_in,
                              void* d_out, int out_size) {
    const float* node_feat = (const float*)d_in[0];
    const float* edge_attr = (const float*)d_in[1];
    const float* enc_W  = (const float*)d_in[2];
    const float* enc_b  = (const float*)d_in[3];
    const float* mlp_W1 = (const float*)d_in[4];
    const float* mlp_b1 = (const float*)d_in[5];
    const float* mlp_W2 = (const float*)d_in[6];
    const float* mlp_b2 = (const float*)d_in[7];
    const float* upd_W1 = (const float*)d_in[8];
    const float* upd_b1 = (const float*)d_in[9];
    const float* upd_W2 = (const float*)d_in[10];
    const float* upd_b2 = (const float*)d_in[11];
    const float* ln_g   = (const float*)d_in[12];
    const float* ln_b   = (const float*)d_in[13];
    const float* out_W1 = (const float*)d_in[14];
    const float* out_b1 = (const float*)d_in[15];
    const float* out_W2 = (const float*)d_in[16];
    const float* out_b2 = (const float*)d_in[17];
    const int*   ei     = (const int*)d_in[18];

    const int N = NODES;
    const int E = EDGES;

    float *px, *ppq, *pinv, *pgate;
    uint32_t *px32, *pH32, *pag32, *pt32, *pwT;
    cudaGetSymbolAddress((void**)&px,    g_x);
    cudaGetSymbolAddress((void**)&px32,  g_x32);
    cudaGetSymbolAddress((void**)&ppq,   g_pq);
    cudaGetSymbolAddress((void**)&pH32,  g_H32);
    cudaGetSymbolAddress((void**)&pag32, g_ag32);
    cudaGetSymbolAddress((void**)&pt32,  g_t32);
    cudaGetSymbolAddress((void**)&pwT,   g_wT);
    cudaGetSymbolAddress((void**)&pinv,  g_invdeg);
    cudaGetSymbolAddress((void**)&pgate, g_gate);

    // instantiations:
    // P:    4ch, bias,              WF          (NO=256)
    // Q:    4ch,                    WF          (NO=256)
    // aggr: 4ch, scale,             W32
    // upd:  8ch dual, bias, relu,   W32
    // ln:   4ch, bias, relu, LN,    WF+W32
    auto gP  = gemm_mma<4, false, true,  false, false, false, true,  false>;
    auto gQ  = gemm_mma<4, false, false, false, false, false, true,  false>;
    auto gAg = gemm_mma<4, false, false, false, true,  false, false, true>;
    auto gUp = gemm_mma<8, true,  true,  true,  false, false, false, true>;
    auto gLn = gemm_mma<4, false, true,  true,  false, true,  true,  true>;

    cudaFuncSetAttribute(gP,  cudaFuncAttributeMaxDynamicSharedMemorySize, GEMM_SMEM_BYTES);
    cudaFuncSetAttribute(gQ,  cudaFuncAttributeMaxDynamicSharedMemorySize, GEMM_SMEM_BYTES);
    cudaFuncSetAttribute(gAg, cudaFuncAttributeMaxDynamicSharedMemorySize, GEMM_SMEM_BYTES);
    cudaFuncSetAttribute(gUp, cudaFuncAttributeMaxDynamicSharedMemorySize, GEMM_SMEM_BYTES);
    cudaFuncSetAttribute(gLn, cudaFuncAttributeMaxDynamicSharedMemorySize, GEMM_SMEM_BYTES);

    // CSR build
    k_detect<<<1, 32>>>(ei);
    k_zero_deg<<<(N + 255) / 256, 256>>>(N);
    k_count<<<(E + 255) / 256, 256>>>(ei, E);
    k_scan1<<<(N + 1023) / 1024, 1024>>>(N);
    k_scan2<<<1, 64>>>((N + 1023) / 1024);
    k_scan3<<<(N + 255) / 256, 256>>>(N);
    k_scatter<<<(E + 255) / 256, 256>>>(ei, edge_attr, E);

    // encoder
    k_encode<<<(N * HID + 255) / 256, 256>>>(node_feat, enc_W, enc_b, N);

    const int gtiles = (N + 127) / 128;

    for (int l = 0; l < NLAYER; l++) {
        const float* W1l = mlp_W1 + (size_t)l * 257 * 128;
        k_repackT<<<6 * 16384 / 256, 256>>>(W1l, mlp_W2 + (size_t)l * 128 * 128,
                                            upd_W1 + (size_t)l * 256 * 128,
                                            upd_W2 + (size_t)l * 128 * 128);

        // P = x @ W1a^T + b1   (fp32, C stride 256, offset 0)
        gP<<<gtiles, 256, GEMM_SMEM_BYTES>>>(
            px32, nullptr, pwT + 0 * 16384, nullptr, mlp_b1 + l * 128,
            nullptr, nullptr, nullptr, nullptr, ppq, nullptr, N, 256);

        // Q = x @ W1b^T        (fp32, C stride 256, offset 128)
        gQ<<<gtiles, 256, GEMM_SMEM_BYTES>>>(
            px32, nullptr, pwT + 1 * 16384, nullptr, nullptr,
            nullptr, nullptr, nullptr, nullptr, ppq + 128, nullptr, N, 256);

        // H[n] = sum relu(P[n] + Q[src] + ea*w1c)  -> tf32 bits
        k_aggr<<<(N + 7) / 8, 256>>>(W1l + 256 * 128, N);

        // aggr = (H @ W2^T) * inv_deg + gate * b2  -> tf32 bits
        gAg<<<gtiles, 256, GEMM_SMEM_BYTES>>>(
            pH32, nullptr, pwT + 2 * 16384, nullptr, mlp_b2 + l * 128,
            pinv, pgate, nullptr, nullptr, nullptr, pag32, N, 128);

        // t = relu(x @ U1a^T + aggr @ U1b^T + b1)  -> tf32 bits
        gUp<<<gtiles, 256, GEMM_SMEM_BYTES>>>(
            px32, pag32, pwT + 3 * 16384, pwT + 4 * 16384, upd_b1 + l * 128,
            nullptr, nullptr, nullptr, nullptr, nullptr, pt32, N, 128);

        // x = relu(LN(t @ U2^T + b2))  -> fp32 + tf32 bits
        gLn<<<gtiles, 256, GEMM_SMEM_BYTES>>>(
            pt32, nullptr, pwT + 5 * 16384, nullptr, upd_b2 + l * 128,
            nullptr, nullptr, ln_g + l * 128, ln_b + l * 128, px, px32, N, 128);
    }

    // readout
    k_zero_gvec<<<1, 128>>>();
    k_mean<<<400, 128>>>(N);
    k_out<<<1, 128>>>(out_W1, out_b1, out_W2, out_b2, (float*)d_out, 1.0f / (float)N);
}

// round 5
// speedup vs baseline: 1.1236x; 1.1236x over previous
#include <cuda_runtime.h>
#include <cstdint>

#define NODES 50000
#define EDGES 800000
#define HID   128
#define NLAYER 3

// ---------------- scratch (static device globals; no allocation) ----------------
__device__ float    g_x   [NODES * HID];       // fp32 node state (readout)
__device__ uint32_t g_x32 [NODES * HID];       // tf32-bit shadow (GEMM A input)
__device__ float    g_pq  [NODES * 2 * HID];   // [P | Q] per node (k_aggr input)
__device__ uint32_t g_H32 [NODES * HID];       // inv_deg * segment_sum(relu_h), tf32 bits
__device__ uint32_t g_t32 [NODES * HID];       // update hidden, tf32 bits
__device__ int   g_esrc[EDGES];
__device__ float g_eea [EDGES];
__device__ int   g_deg [NODES];
__device__ int   g_tmp [NODES];
__device__ int   g_rowptr[NODES + 1];
__device__ int   g_cursor[NODES];
__device__ float g_invdeg[NODES];
__device__ float g_gate  [NODES];
__device__ uint32_t g_wT[5 * HID * HID];   // tf32 B^T: 0=W1a 1=W1b 2=U1a 3=U2 4=Wc
__device__ float g_bc  [HID];              // b2 @ U1b
__device__ float g_gvec[HID];
__device__ int   g_is64;
__device__ int   g_bsum[64];
__device__ int   g_boff[64];

// ================= helpers =================
__device__ __forceinline__ uint32_t cvt_tf32(float x) {
    uint32_t r;
    asm("cvt.rna.tf32.f32 %0, %1;" : "=r"(r) : "f"(x));
    return r;
}
__device__ __forceinline__ void mma8(float* c, const uint32_t* a, const uint32_t* b) {
    asm volatile(
        "mma.sync.aligned.m16n8k8.row.col.f32.tf32.tf32.f32 "
        "{%0,%1,%2,%3},{%4,%5,%6,%7},{%8,%9},{%0,%1,%2,%3};"
        : "+f"(c[0]), "+f"(c[1]), "+f"(c[2]), "+f"(c[3])
        : "r"(a[0]), "r"(a[1]), "r"(a[2]), "r"(a[3]), "r"(b[0]), "r"(b[1]));
}

// ================= CSR build =================
__global__ void k_detect(const int* __restrict__ ei) {
    if (blockIdx.x == 0 && threadIdx.x == 0) {
        int z = 1;
        #pragma unroll
        for (int i = 1; i < 16; i += 2) if (ei[i] != 0) z = 0;
        g_is64 = z;
    }
}
__global__ void k_zero_deg(int N) {
    int i = blockIdx.x * blockDim.x + threadIdx.x;
    if (i < N) g_deg[i] = 0;
}
__global__ void k_count(const int* __restrict__ ei, int E) {
    int e = blockIdx.x * blockDim.x + threadIdx.x;
    if (e >= E) return;
    int is64 = g_is64;
    int dst = is64 ? ei[2 * E + 2 * e] : ei[E + e];
    atomicAdd(&g_deg[dst], 1);
}
__global__ void k_scan1(int N) {
    __shared__ int s[1024];
    int tid = threadIdx.x;
    int i = blockIdx.x * 1024 + tid;
    int v = (i < N) ? g_deg[i] : 0;
    s[tid] = v;
    __syncthreads();
    for (int off = 1; off < 1024; off <<= 1) {
        int t = (tid >= off) ? s[tid - off] : 0;
        __syncthreads();
        s[tid] += t;
        __syncthreads();
    }
    if (i < N) g_tmp[i] = s[tid];
    if (tid == 1023) g_bsum[blockIdx.x] = s[1023];
}
__global__ void k_scan2(int nb) {
    __shared__ int s[64];
    int tid = threadIdx.x;
    int v = (tid < nb) ? g_bsum[tid] : 0;
    s[tid] = v;
    __syncthreads();
    for (int off = 1; off < 64; off <<= 1) {
        int t = (tid >= off) ? s[tid - off] : 0;
        __syncthreads();
        s[tid] += t;
        __syncthreads();
    }
    g_boff[tid] = s[tid] - v;   // exclusive
}
__global__ void k_scan3(int N) {
    int i = blockIdx.x * blockDim.x + threadIdx.x;
    if (i >= N) return;
    int incl = g_tmp[i] + g_boff[i >> 10];
    int d = g_deg[i];
    int excl = incl - d;
    g_rowptr[i] = excl;
    g_cursor[i] = excl;
    g_invdeg[i] = 1.0f / fmaxf((float)d, 1.0f);
    g_gate[i]   = (d > 0) ? 1.0f : 0.0f;
    if (i == N - 1) g_rowptr[N] = incl;
}
__global__ void k_scatter(const int* __restrict__ ei, const float* __restrict__ ea, int E) {
    int e = blockIdx.x * blockDim.x + threadIdx.x;
    if (e >= E) return;
    int is64 = g_is64;
    int src = is64 ? ei[2 * e]         : ei[e];
    int dst = is64 ? ei[2 * E + 2 * e] : ei[E + e];
    int pos = atomicAdd(&g_cursor[dst], 1);
    g_esrc[pos] = src;
    g_eea[pos]  = ea[e];
}

// ================= encoder =================
__global__ void k_encode(const float* __restrict__ nf, const float* __restrict__ W,
                         const float* __restrict__ b, int N) {
    int t = blockIdx.x * blockDim.x + threadIdx.x;
    if (t >= N * HID) return;
    int n = t >> 7, c = t & 127;
    float acc = b[c];
    #pragma unroll
    for (int k = 0; k < 5; k++) acc = fmaf(nf[n * 5 + k], W[k * HID + c], acc);
    g_x[t]   = acc;
    g_x32[t] = cvt_tf32(acc);
}

// ================= per-layer weight repack (transpose, to tf32 bits) =================
// slots: 0=W1a, 1=W1b, 2=U1a, 3=U2
__global__ void k_repackT(const float* __restrict__ W1, const float* __restrict__ U1,
                          const float* __restrict__ U2) {
    int t = blockIdx.x * blockDim.x + threadIdx.x;   // < 4*16384
    int w = t >> 14;
    int j = (t >> 7) & 127;
    int k = t & 127;
    float v;
    switch (w) {
        case 0:  v = W1[k * 128 + j];          break;
        case 1:  v = W1[(128 + k) * 128 + j];  break;
        case 2:  v = U1[k * 128 + j];          break;
        default: v = U2[k * 128 + j];          break;
    }
    g_wT[t] = cvt_tf32(v);
}

// ================= fused small weight: Wc = W2 @ U1b, bc = b2 @ U1b =================
// block k (128 blocks), thread j: Wc[k][j] = sum_t W2[k][t]*U1[(128+t)*128+j]
__global__ void k_fuseW(const float* __restrict__ W2, const float* __restrict__ U1,
                        const float* __restrict__ b2) {
    __shared__ float w2row[128];
    int k = blockIdx.x, j = threadIdx.x;
    w2row[j] = W2[k * 128 + j];
    __syncthreads();
    float acc = 0.f;
    #pragma unroll 8
    for (int t = 0; t < 128; t++) acc = fmaf(w2row[t], U1[(128 + t) * 128 + j], acc);
    g_wT[4 * 16384 + j * 128 + k] = cvt_tf32(acc);
    if (k == 0) {
        float bacc = 0.f;
        #pragma unroll 8
        for (int t = 0; t < 128; t++) bacc = fmaf(b2[t], U1[(128 + t) * 128 + j], bacc);
        g_bc[j] = bacc;
    }
}

// ================= tf32 mma.sync GEMM: 128x128 CTA tile =================
// 256 threads = 8 warps (2m x 4n); warp tile 64x32; mma m16n8k8; K chunks of 64.
// Inputs pre-converted tf32 bits (no cvt in mainloop).
// MODE 0 (PQ):  gridDim.y=2 selects B (W1a/W1b) and output half; bias on y==0; fp32 out stride 256
// MODE 1 (UPD): dual pass A1@B1 + A2@B2; v = relu(v + bias[col] + rowgate[m]*bias2[col]); tf32 out
// MODE 2 (LN):  v = relu(LN(v + bias)*lng + lnb); fp32 out + tf32 out
#define SM_STRIDE 68
#define GEMM_SMEM_BYTES (2 * 128 * SM_STRIDE * 4)

template<int MODE>
__global__ void __launch_bounds__(256, 2)
gemm_mma(const uint32_t* __restrict__ A1, const uint32_t* __restrict__ A2,
         const uint32_t* __restrict__ B1, const uint32_t* __restrict__ B2,
         const float* __restrict__ bias, const float* __restrict__ bias2,
         const float* __restrict__ rowgate,
         const float* __restrict__ lng, const float* __restrict__ lnb,
         float* __restrict__ Cf, uint32_t* __restrict__ C32, int M)
{
    extern __shared__ uint32_t sm[];
    uint32_t* As = sm;                       // [128][68]
    uint32_t* Bs = sm + 128 * SM_STRIDE;

    const int tid = threadIdx.x;
    const int wid = tid >> 5, lane = tid & 31;
    const int g = lane >> 2, tig = lane & 3;
    const int warp_m = wid >> 2, warp_n = wid & 3;
    const int mw = warp_m * 64, nw = warp_n * 32;
    const int m0 = blockIdx.x * 128;
    const int NO     = (MODE == 0) ? 256 : 128;
    const int colOff = (MODE == 0) ? blockIdx.y * 128 : 0;

    float acc[4][4][4];
    #pragma unroll
    for (int i = 0; i < 4; i++)
        #pragma unroll
        for (int j = 0; j < 4; j++)
            #pragma unroll
            for (int r = 0; r < 4; r++) acc[i][j][r] = 0.0f;

    const int npass = (MODE == 1) ? 2 : 1;
    for (int p = 0; p < npass; p++) {
        const uint32_t* A = (MODE == 1 && p) ? A2 : A1;
        const uint32_t* B;
        if constexpr (MODE == 0) B = (blockIdx.y == 0) ? B1 : B2;
        else                     B = (MODE == 1 && p) ? B2 : B1;
        for (int c = 0; c < 2; c++) {
            __syncthreads();
            #pragma unroll
            for (int u = 0; u < 8; u++) {
                int linear = u * 256 + tid;          // 0..2047
                int row = linear >> 4;
                int q   = linear & 15;
                uint4 av = make_uint4(0u, 0u, 0u, 0u);
                if (m0 + row < M)
                    av = *(const uint4*)&A[(size_t)(m0 + row) * 128 + c * 64 + q * 4];
                *(uint4*)&As[row * SM_STRIDE + q * 4] = av;
                *(uint4*)&Bs[row * SM_STRIDE + q * 4] =
                    *(const uint4*)&B[(size_t)row * 128 + c * 64 + q * 4];
            }
            __syncthreads();
            #pragma unroll
            for (int ks = 0; ks < 8; ks++) {
                const int k0 = ks * 8;
                uint32_t af[4][4], bf[4][2];
                #pragma unroll
                for (int i = 0; i < 4; i++) {
                    const uint32_t* base = &As[(mw + i * 16 + g) * SM_STRIDE + k0 + tig];
                    af[i][0] = base[0];
                    af[i][1] = base[8 * SM_STRIDE];
                    af[i][2] = base[4];
                    af[i][3] = base[8 * SM_STRIDE + 4];
                }
                #pragma unroll
                for (int j = 0; j < 4; j++) {
                    const uint32_t* base = &Bs[(nw + j * 8 + g) * SM_STRIDE + k0 + tig];
                    bf[j][0] = base[0];
                    bf[j][1] = base[4];
                }
                #pragma unroll
                for (int i = 0; i < 4; i++)
                    #pragma unroll
                    for (int j = 0; j < 4; j++)
                        mma8(acc[i][j], af[i], bf[j]);
            }
        }
    }

    // ---------------- epilogue ----------------
    float bcol[4][2];
    #pragma unroll
    for (int j = 0; j < 4; j++) {
        int col = nw + j * 8 + 2 * tig;
        bool haveb = (MODE != 0) || (blockIdx.y == 0);
        bcol[j][0] = haveb ? bias[col]     : 0.0f;
        bcol[j][1] = haveb ? bias[col + 1] : 0.0f;
    }

    if constexpr (MODE == 2) {
        __syncthreads();
        float* sS  = (float*)sm;            // [128][4]
        float* sS2 = (float*)(sm + 512);
        float gcol[4][2], lcol[4][2];
        #pragma unroll
        for (int j = 0; j < 4; j++) {
            int col = nw + j * 8 + 2 * tig;
            gcol[j][0] = lng[col];     gcol[j][1] = lng[col + 1];
            lcol[j][0] = lnb[col];     lcol[j][1] = lnb[col + 1];
        }
        #pragma unroll
        for (int i = 0; i < 4; i++) {
            #pragma unroll
            for (int h = 0; h < 2; h++) {
                float s = 0.f, s2 = 0.f;
                #pragma unroll
                for (int j = 0; j < 4; j++) {
                    #pragma unroll
                    for (int r = 0; r < 2; r++) {
                        float v = acc[i][j][2 * h + r] + bcol[j][r];
                        s += v; s2 += v * v;
                    }
                }
                s  += __shfl_xor_sync(0xffffffffu, s, 1);
                s  += __shfl_xor_sync(0xffffffffu, s, 2);
                s2 += __shfl_xor_sync(0xffffffffu, s2, 1);
                s2 += __shfl_xor_sync(0xffffffffu, s2, 2);
                if (tig == 0) {
                    int rl = mw + i * 16 + g + 8 * h;
                    sS [rl * 4 + warp_n] = s;
                    sS2[rl * 4 + warp_n] = s2;
                }
            }
        }
        __syncthreads();
        #pragma unroll
        for (int i = 0; i < 4; i++) {
            #pragma unroll
            for (int h = 0; h < 2; h++) {
                int rl = mw + i * 16 + g + 8 * h;
                int row = m0 + rl;
                float s  = sS [rl * 4] + sS [rl * 4 + 1] + sS [rl * 4 + 2] + sS [rl * 4 + 3];
                float s2 = sS2[rl * 4] + sS2[rl * 4 + 1] + sS2[rl * 4 + 2] + sS2[rl * 4 + 3];
                float mu   = s * (1.0f / 128.0f);
                float var  = s2 * (1.0f / 128.0f) - mu * mu;
                float rstd = rsqrtf(var + 1e-5f);
                if (row < M) {
                    #pragma unroll
                    for (int j = 0; j < 4; j++) {
                        int col = nw + j * 8 + 2 * tig;
                        float v0 = fmaxf((acc[i][j][2*h]   + bcol[j][0] - mu) * rstd * gcol[j][0] + lcol[j][0], 0.f);
                        float v1 = fmaxf((acc[i][j][2*h+1] + bcol[j][1] - mu) * rstd * gcol[j][1] + lcol[j][1], 0.f);
                        float2 o; o.x = v0; o.y = v1;
                        *(float2*)&Cf[(size_t)row * 128 + col] = o;
                        uint2 u; u.x = cvt_tf32(v0); u.y = cvt_tf32(v1);
                        *(uint2*)&C32[(size_t)row * 128 + col] = u;
                    }
                }
            }
        }
    } else {
        float b2col[4][2];
        if constexpr (MODE == 1) {
            #pragma unroll
            for (int j = 0; j < 4; j++) {
                int col = nw + j * 8 + 2 * tig;
                b2col[j][0] = bias2[col];
                b2col[j][1] = bias2[col + 1];
            }
        }
        #pragma unroll
        for (int i = 0; i < 4; i++) {
            #pragma unroll
            for (int h = 0; h < 2; h++) {
                int row = m0 + mw + i * 16 + g + 8 * h;
                if (row >= M) continue;
                float gt = (MODE == 1) ? rowgate[row] : 0.f;
                #pragma unroll
                for (int j = 0; j < 4; j++) {
                    int col = colOff + nw + j * 8 + 2 * tig;
                    float v0 = acc[i][j][2 * h] + bcol[j][0];
                    float v1 = acc[i][j][2 * h + 1] + bcol[j][1];
                    if constexpr (MODE == 1) {
                        v0 = fmaxf(fmaf(gt, b2col[j][0], v0), 0.f);
                        v1 = fmaxf(fmaf(gt, b2col[j][1], v1), 0.f);
                        uint2 u; u.x = cvt_tf32(v0); u.y = cvt_tf32(v1);
                        *(uint2*)&C32[(size_t)row * 128 + col] = u;
                    } else {
                        float2 o; o.x = v0; o.y = v1;
                        *(float2*)&Cf[(size_t)row * 256 + col] = o;
                    }
                }
            }
        }
    }
}

// ================= edge aggregation: warp per node =================
// H32[n] = tf32( inv_deg[n] * sum relu(P[n] + Q[src] + ea*w1c) )
__global__ void __launch_bounds__(256) k_aggr(const float* __restrict__ w1c, int N) {
    int warp = (blockIdx.x * blockDim.x + threadIdx.x) >> 5;
    int lane = threadIdx.x & 31;
    if (warp >= N) return;
    int node = warp;
    float4 p = *(const float4*)&g_pq[(size_t)node * 256 + lane * 4];
    float4 w = *(const float4*)&w1c[lane * 4];
    float4 acc = make_float4(0.f, 0.f, 0.f, 0.f);
    int s0 = g_rowptr[node], s1 = g_rowptr[node + 1];
    for (int j = s0; j < s1; j++) {
        int src  = g_esrc[j];
        float ea = g_eea[j];
        float4 q = *(const float4*)&g_pq[(size_t)src * 256 + 128 + lane * 4];
        acc.x += fmaxf(fmaf(ea, w.x, p.x + q.x), 0.0f);
        acc.y += fmaxf(fmaf(ea, w.y, p.y + q.y), 0.0f);
        acc.z += fmaxf(fmaf(ea, w.z, p.z + q.z), 0.0f);
        acc.w += fmaxf(fmaf(ea, w.w, p.w + q.w), 0.0f);
    }
    float inv = g_invdeg[node];
    uint4 u;
    u.x = cvt_tf32(acc.x * inv); u.y = cvt_tf32(acc.y * inv);
    u.z = cvt_tf32(acc.z * inv); u.w = cvt_tf32(acc.w * inv);
    *(uint4*)&g_H32[(size_t)node * 128 + lane * 4] = u;
}

// ================= readout =================
__global__ void k_zero_gvec() { if (threadIdx.x < 128) g_gvec[threadIdx.x] = 0.0f; }
__global__ void k_mean(int N) {
    int c = threadIdx.x;
    int rows_per = (N + gridDim.x - 1) / gridDim.x;
    int r0 = blockIdx.x * rows_per;
    int r1 = min(r0 + rows_per, N);
    float s = 0.0f;
    for (int r = r0; r < r1; r++) s += g_x[(size_t)r * 128 + c];
    atomicAdd(&g_gvec[c], s);
}
__global__ void k_out(const float* __restrict__ W1, const float* __restrict__ b1,
                      const float* __restrict__ W2, const float* __restrict__ b2,
                      float* __restrict__ out, float invN) {
    __shared__ float gs[128];
    __shared__ float hs[128];
    int c = threadIdx.x;
    gs[c] = g_gvec[c] * invN;
    __syncthreads();
    float a = b1[c];
    #pragma unroll 8
    for (int k = 0; k < 128; k++) a = fmaf(gs[k], W1[k * 128 + c], a);
    hs[c] = fmaxf(a, 0.0f);
    __syncthreads();
    float o = b2[c];
    #pragma unroll 8
    for (int k = 0; k < 128; k++) o = fmaf(hs[k], W2[k * 128 + c], o);
    out[c] = o;
}

// ================= launch =================
extern "C" void kernel_launch(void* const* d_in, const int* in_sizes, int n_in,
                              void* d_out, int out_size) {
    const float* node_feat = (const float*)d_in[0];
    const float* edge_attr = (const float*)d_in[1];
    const float* enc_W  = (const float*)d_in[2];
    const float* enc_b  = (const float*)d_in[3];
    const float* mlp_W1 = (const float*)d_in[4];
    const float* mlp_b1 = (const float*)d_in[5];
    const float* mlp_W2 = (const float*)d_in[6];
    const float* mlp_b2 = (const float*)d_in[7];
    const float* upd_W1 = (const float*)d_in[8];
    const float* upd_b1 = (const float*)d_in[9];
    const float* upd_W2 = (const float*)d_in[10];
    const float* upd_b2 = (const float*)d_in[11];
    const float* ln_g   = (const float*)d_in[12];
    const float* ln_b   = (const float*)d_in[13];
    const float* out_W1 = (const float*)d_in[14];
    const float* out_b1 = (const float*)d_in[15];
    const float* out_W2 = (const float*)d_in[16];
    const float* out_b2 = (const float*)d_in[17];
    const int*   ei     = (const int*)d_in[18];

    const int N = NODES;
    const int E = EDGES;

    float *px, *ppq, *pbc, *pgate;
    uint32_t *px32, *pH32, *pt32, *pwT;
    cudaGetSymbolAddress((void**)&px,    g_x);
    cudaGetSymbolAddress((void**)&px32,  g_x32);
    cudaGetSymbolAddress((void**)&ppq,   g_pq);
    cudaGetSymbolAddress((void**)&pH32,  g_H32);
    cudaGetSymbolAddress((void**)&pt32,  g_t32);
    cudaGetSymbolAddress((void**)&pwT,   g_wT);
    cudaGetSymbolAddress((void**)&pbc,   g_bc);
    cudaGetSymbolAddress((void**)&pgate, g_gate);

    cudaFuncSetAttribute(gemm_mma<0>, cudaFuncAttributeMaxDynamicSharedMemorySize, GEMM_SMEM_BYTES);
    cudaFuncSetAttribute(gemm_mma<1>, cudaFuncAttributeMaxDynamicSharedMemorySize, GEMM_SMEM_BYTES);
    cudaFuncSetAttribute(gemm_mma<2>, cudaFuncAttributeMaxDynamicSharedMemorySize, GEMM_SMEM_BYTES);

    // CSR build
    k_detect<<<1, 32>>>(ei);
    k_zero_deg<<<(N + 255) / 256, 256>>>(N);
    k_count<<<(E + 255) / 256, 256>>>(ei, E);
    k_scan1<<<(N + 1023) / 1024, 1024>>>(N);
    k_scan2<<<1, 64>>>((N + 1023) / 1024);
    k_scan3<<<(N + 255) / 256, 256>>>(N);
    k_scatter<<<(E + 255) / 256, 256>>>(ei, edge_attr, E);

    // encoder
    k_encode<<<(N * HID + 255) / 256, 256>>>(node_feat, enc_W, enc_b, N);

    const int gtiles = (N + 127) / 128;

    for (int l = 0; l < NLAYER; l++) {
        const float* W1l = mlp_W1 + (size_t)l * 257 * 128;
        const float* U1l = upd_W1 + (size_t)l * 256 * 128;
        k_repackT<<<4 * 16384 / 256, 256>>>(W1l, U1l, upd_W2 + (size_t)l * 128 * 128);
        k_fuseW<<<128, 128>>>(mlp_W2 + (size_t)l * 128 * 128, U1l, mlp_b2 + l * 128);

        // [P|Q] = x @ [W1a|W1b]^T (+b1 on P); fp32 out stride 256
        gemm_mma<0><<<dim3(gtiles, 2), 256, GEMM_SMEM_BYTES>>>(
            px32, nullptr, pwT + 0 * 16384, pwT + 1 * 16384, mlp_b1 + l * 128,
            nullptr, nullptr, nullptr, nullptr, ppq, nullptr, N);

        // Hn[n] = inv_deg * sum relu(P[n] + Q[src] + ea*w1c)  -> tf32 bits
        k_aggr<<<(N + 7) / 8, 256>>>(W1l + 256 * 128, N);

        // t = relu(x @ U1a^T + Hn @ Wc^T + b1 + gate*bc)  -> tf32 bits
        gemm_mma<1><<<gtiles, 256, GEMM_SMEM_BYTES>>>(
            px32, pH32, pwT + 2 * 16384, pwT + 4 * 16384, upd_b1 + l * 128,
            pbc, pgate, nullptr, nullptr, nullptr, pt32, N);

        // x = relu(LN(t @ U2^T + b2))  -> fp32 + tf32 bits
        gemm_mma<2><<<gtiles, 256, GEMM_SMEM_BYTES>>>(
            pt32, nullptr, pwT + 3 * 16384, nullptr, upd_b2 + l * 128,
            nullptr, nullptr, ln_g + l * 128, ln_b + l * 128, px, px32, N);
    }

    // readout
    k_zero_gvec<<<1, 128>>>();
    k_mean<<<400, 128>>>(N);
    k_out<<<1, 128>>>(out_W1, out_b1, out_W2, out_b2, (float*)d_out, 1.0f / (float)N);
}

// round 6
// speedup vs baseline: 1.1377x; 1.0126x over previous
#include <cuda_runtime.h>
#include <cuda_fp16.h>
#include <cstdint>

#define NODES 50000
#define EDGES 800000
#define HID   128
#define NLAYER 3

// ---------------- scratch (static device globals; no allocation) ----------------
__device__ float    g_x   [NODES * HID];       // fp32 node state (readout)
__device__ uint32_t g_x32 [NODES * HID];       // tf32-bit shadow (GEMM A input)
__device__ float    g_p   [NODES * HID];       // P per node (fp32, k_aggr input)
__device__ __half   g_qh  [NODES * HID];       // Q per node (fp16, gathered per edge)
__device__ uint32_t g_H32 [NODES * HID];       // inv_deg * segment_sum(relu_h), tf32 bits
__device__ uint32_t g_t32 [NODES * HID];       // update hidden, tf32 bits
__device__ int   g_esrc[EDGES];
__device__ float g_eea [EDGES];
__device__ int   g_deg [NODES];
__device__ int   g_tmp [NODES];
__device__ int   g_rowptr[NODES + 1];
__device__ int   g_cursor[NODES];
__device__ float g_invdeg[NODES];
__device__ float g_gate  [NODES];
__device__ uint32_t g_wT[5 * HID * HID];   // tf32 B^T: 0=W1a 1=W1b 2=U1a 3=U2 4=Wc
__device__ float g_bc  [HID];              // b2 @ U1b
__device__ float g_gvec[HID];
__device__ int   g_is64;
__device__ int   g_bsum[64];
__device__ int   g_boff[64];

// ================= helpers =================
__device__ __forceinline__ uint32_t cvt_tf32(float x) {
    uint32_t r;
    asm("cvt.rna.tf32.f32 %0, %1;" : "=r"(r) : "f"(x));
    return r;
}
__device__ __forceinline__ void mma8(float* c, const uint32_t* a, const uint32_t* b) {
    asm volatile(
        "mma.sync.aligned.m16n8k8.row.col.f32.tf32.tf32.f32 "
        "{%0,%1,%2,%3},{%4,%5,%6,%7},{%8,%9},{%0,%1,%2,%3};"
        : "+f"(c[0]), "+f"(c[1]), "+f"(c[2]), "+f"(c[3])
        : "r"(a[0]), "r"(a[1]), "r"(a[2]), "r"(a[3]), "r"(b[0]), "r"(b[1]));
}

// ================= CSR build =================
__global__ void k_detect(const int* __restrict__ ei) {
    if (blockIdx.x == 0 && threadIdx.x == 0) {
        int z = 1;
        #pragma unroll
        for (int i = 1; i < 16; i += 2) if (ei[i] != 0) z = 0;
        g_is64 = z;
    }
}
__global__ void k_zero_deg(int N) {
    int i = blockIdx.x * blockDim.x + threadIdx.x;
    if (i < N) g_deg[i] = 0;
}
__global__ void k_count(const int* __restrict__ ei, int E) {
    int e = blockIdx.x * blockDim.x + threadIdx.x;
    if (e >= E) return;
    int is64 = g_is64;
    int dst = is64 ? ei[2 * E + 2 * e] : ei[E + e];
    atomicAdd(&g_deg[dst], 1);
}
__global__ void k_scan1(int N) {
    __shared__ int s[1024];
    int tid = threadIdx.x;
    int i = blockIdx.x * 1024 + tid;
    int v = (i < N) ? g_deg[i] : 0;
    s[tid] = v;
    __syncthreads();
    for (int off = 1; off < 1024; off <<= 1) {
        int t = (tid >= off) ? s[tid - off] : 0;
        __syncthreads();
        s[tid] += t;
        __syncthreads();
    }
    if (i < N) g_tmp[i] = s[tid];
    if (tid == 1023) g_bsum[blockIdx.x] = s[1023];
}
__global__ void k_scan2(int nb) {
    __shared__ int s[64];
    int tid = threadIdx.x;
    int v = (tid < nb) ? g_bsum[tid] : 0;
    s[tid] = v;
    __syncthreads();
    for (int off = 1; off < 64; off <<= 1) {
        int t = (tid >= off) ? s[tid - off] : 0;
        __syncthreads();
        s[tid] += t;
        __syncthreads();
    }
    g_boff[tid] = s[tid] - v;   // exclusive
}
__global__ void k_scan3(int N) {
    int i = blockIdx.x * blockDim.x + threadIdx.x;
    if (i >= N) return;
    int incl = g_tmp[i] + g_boff[i >> 10];
    int d = g_deg[i];
    int excl = incl - d;
    g_rowptr[i] = excl;
    g_cursor[i] = excl;
    g_invdeg[i] = 1.0f / fmaxf((float)d, 1.0f);
    g_gate[i]   = (d > 0) ? 1.0f : 0.0f;
    if (i == N - 1) g_rowptr[N] = incl;
}
__global__ void k_scatter(const int* __restrict__ ei, const float* __restrict__ ea, int E) {
    int e = blockIdx.x * blockDim.x + threadIdx.x;
    if (e >= E) return;
    int is64 = g_is64;
    int src = is64 ? ei[2 * e]         : ei[e];
    int dst = is64 ? ei[2 * E + 2 * e] : ei[E + e];
    int pos = atomicAdd(&g_cursor[dst], 1);
    g_esrc[pos] = src;
    g_eea[pos]  = ea[e];
}

// ================= encoder =================
__global__ void k_encode(const float* __restrict__ nf, const float* __restrict__ W,
                         const float* __restrict__ b, int N) {
    int t = blockIdx.x * blockDim.x + threadIdx.x;
    if (t >= N * HID) return;
    int n = t >> 7, c = t & 127;
    float acc = b[c];
    #pragma unroll
    for (int k = 0; k < 5; k++) acc = fmaf(nf[n * 5 + k], W[k * HID + c], acc);
    g_x[t]   = acc;
    g_x32[t] = cvt_tf32(acc);
}

// ================= per-layer weight repack (transpose, to tf32 bits) =================
// slots: 0=W1a, 1=W1b, 2=U1a, 3=U2
__global__ void k_repackT(const float* __restrict__ W1, const float* __restrict__ U1,
                          const float* __restrict__ U2) {
    int t = blockIdx.x * blockDim.x + threadIdx.x;   // < 4*16384
    int w = t >> 14;
    int j = (t >> 7) & 127;
    int k = t & 127;
    float v;
    switch (w) {
        case 0:  v = W1[k * 128 + j];          break;
        case 1:  v = W1[(128 + k) * 128 + j];  break;
        case 2:  v = U1[k * 128 + j];          break;
        default: v = U2[k * 128 + j];          break;
    }
    g_wT[t] = cvt_tf32(v);
}

// ================= fused small weight: Wc = W2 @ U1b, bc = b2 @ U1b =================
__global__ void k_fuseW(const float* __restrict__ W2, const float* __restrict__ U1,
                        const float* __restrict__ b2) {
    __shared__ float w2row[128];
    int k = blockIdx.x, j = threadIdx.x;
    w2row[j] = W2[k * 128 + j];
    __syncthreads();
    float acc = 0.f;
    #pragma unroll 8
    for (int t = 0; t < 128; t++) acc = fmaf(w2row[t], U1[(128 + t) * 128 + j], acc);
    g_wT[4 * 16384 + j * 128 + k] = cvt_tf32(acc);
    if (k == 0) {
        float bacc = 0.f;
        #pragma unroll 8
        for (int t = 0; t < 128; t++) bacc = fmaf(b2[t], U1[(128 + t) * 128 + j], bacc);
        g_bc[j] = bacc;
    }
}

// ================= tf32 mma.sync GEMM: 64x128 CTA tile =================
// 256 threads = 8 warps (2m x 4n); warp tile 32x32; mma m16n8k8; K chunks of 64.
// 52 KB smem, __launch_bounds__(256,3) -> 3 CTAs/SM (444 concurrent, kills wave quantization).
// MODE 0 (PQ):  gridDim.y: y=0 -> P = A@W1a^T + b1 (fp32, g_p); y=1 -> Q = A@W1b^T (fp16, g_qh)
// MODE 1 (UPD): dual pass A1@B1 + A2@B2; v = relu(v + bias + rowgate[m]*bias2); tf32 out
// MODE 2 (LN):  v = relu(LN(v + bias)*lng + lnb); fp32 out + tf32 out
#define SM_STRIDE 68
#define GEMM_SMEM_BYTES ((64 + 128) * SM_STRIDE * 4)

template<int MODE>
__global__ void __launch_bounds__(256, 3)
gemm_mma(const uint32_t* __restrict__ A1, const uint32_t* __restrict__ A2,
         const uint32_t* __restrict__ B1, const uint32_t* __restrict__ B2,
         const float* __restrict__ bias, const float* __restrict__ bias2,
         const float* __restrict__ rowgate,
         const float* __restrict__ lng, const float* __restrict__ lnb,
         float* __restrict__ Cf, uint32_t* __restrict__ C32,
         __half* __restrict__ Ch, int M)
{
    extern __shared__ uint32_t sm[];
    uint32_t* As = sm;                       // [64][68]
    uint32_t* Bs = sm + 64 * SM_STRIDE;      // [128][68]

    const int tid = threadIdx.x;
    const int wid = tid >> 5, lane = tid & 31;
    const int g = lane >> 2, tig = lane & 3;
    const int warp_m = wid >> 2, warp_n = wid & 3;
    const int mw = warp_m * 32, nw = warp_n * 32;
    const int m0 = blockIdx.x * 64;

    float acc[2][4][4];
    #pragma unroll
    for (int i = 0; i < 2; i++)
        #pragma unroll
        for (int j = 0; j < 4; j++)
            #pragma unroll
            for (int r = 0; r < 4; r++) acc[i][j][r] = 0.0f;

    const int npass = (MODE == 1) ? 2 : 1;
    for (int p = 0; p < npass; p++) {
        const uint32_t* A = (MODE == 1 && p) ? A2 : A1;
        const uint32_t* B;
        if constexpr (MODE == 0) B = (blockIdx.y == 0) ? B1 : B2;
        else                     B = (MODE == 1 && p) ? B2 : B1;
        for (int c = 0; c < 2; c++) {
            __syncthreads();
            // A tile: 64 rows x 16 float4
            #pragma unroll
            for (int u = 0; u < 4; u++) {
                int linear = u * 256 + tid;          // 0..1023
                int row = linear >> 4;
                int q   = linear & 15;
                uint4 av = make_uint4(0u, 0u, 0u, 0u);
                if (m0 + row < M)
                    av = *(const uint4*)&A[(size_t)(m0 + row) * 128 + c * 64 + q * 4];
                *(uint4*)&As[row * SM_STRIDE + q * 4] = av;
            }
            // B chunk: 128 rows x 16 float4
            #pragma unroll
            for (int u = 0; u < 8; u++) {
                int linear = u * 256 + tid;          // 0..2047
                int row = linear >> 4;
                int q   = linear & 15;
                *(uint4*)&Bs[row * SM_STRIDE + q * 4] =
                    *(const uint4*)&B[(size_t)row * 128 + c * 64 + q * 4];
            }
            __syncthreads();
            #pragma unroll
            for (int ks = 0; ks < 8; ks++) {
                const int k0 = ks * 8;
                uint32_t af[2][4], bf[4][2];
                #pragma unroll
                for (int i = 0; i < 2; i++) {
                    const uint32_t* base = &As[(mw + i * 16 + g) * SM_STRIDE + k0 + tig];
                    af[i][0] = base[0];
                    af[i][1] = base[8 * SM_STRIDE];
                    af[i][2] = base[4];
                    af[i][3] = base[8 * SM_STRIDE + 4];
                }
                #pragma unroll
                for (int j = 0; j < 4; j++) {
                    const uint32_t* base = &Bs[(nw + j * 8 + g) * SM_STRIDE + k0 + tig];
                    bf[j][0] = base[0];
                    bf[j][1] = base[4];
                }
                #pragma unroll
                for (int i = 0; i < 2; i++)
                    #pragma unroll
                    for (int j = 0; j < 4; j++)
                        mma8(acc[i][j], af[i], bf[j]);
            }
        }
    }

    // ---------------- epilogue ----------------
    float bcol[4][2];
    #pragma unroll
    for (int j = 0; j < 4; j++) {
        int col = nw + j * 8 + 2 * tig;
        bool haveb = (MODE != 0) || (blockIdx.y == 0);
        bcol[j][0] = haveb ? bias[col]     : 0.0f;
        bcol[j][1] = haveb ? bias[col + 1] : 0.0f;
    }

    if constexpr (MODE == 2) {
        __syncthreads();
        float* sS  = (float*)sm;            // [64][4]
        float* sS2 = (float*)(sm + 256);
        float gcol[4][2], lcol[4][2];
        #pragma unroll
        for (int j = 0; j < 4; j++) {
            int col = nw + j * 8 + 2 * tig;
            gcol[j][0] = lng[col];     gcol[j][1] = lng[col + 1];
            lcol[j][0] = lnb[col];     lcol[j][1] = lnb[col + 1];
        }
        #pragma unroll
        for (int i = 0; i < 2; i++) {
            #pragma unroll
            for (int h = 0; h < 2; h++) {
                float s = 0.f, s2 = 0.f;
                #pragma unroll
                for (int j = 0; j < 4; j++) {
                    #pragma unroll
                    for (int r = 0; r < 2; r++) {
                        float v = acc[i][j][2 * h + r] + bcol[j][r];
                        s += v; s2 += v * v;
                    }
                }
                s  += __shfl_xor_sync(0xffffffffu, s, 1);
                s  += __shfl_xor_sync(0xffffffffu, s, 2);
                s2 += __shfl_xor_sync(0xffffffffu, s2, 1);
                s2 += __shfl_xor_sync(0xffffffffu, s2, 2);
                if (tig == 0) {
                    int rl = mw + i * 16 + g + 8 * h;
                    sS [rl * 4 + warp_n] = s;
                    sS2[rl * 4 + warp_n] = s2;
                }
            }
        }
        __syncthreads();
        #pragma unroll
        for (int i = 0; i < 2; i++) {
            #pragma unroll
            for (int h = 0; h < 2; h++) {
                int rl = mw + i * 16 + g + 8 * h;
                int row = m0 + rl;
                float s  = sS [rl * 4] + sS [rl * 4 + 1] + sS [rl * 4 + 2] + sS [rl * 4 + 3];
                float s2 = sS2[rl * 4] + sS2[rl * 4 + 1] + sS2[rl * 4 + 2] + sS2[rl * 4 + 3];
                float mu   = s * (1.0f / 128.0f);
                float var  = s2 * (1.0f / 128.0f) - mu * mu;
                float rstd = rsqrtf(var + 1e-5f);
                if (row < M) {
                    #pragma unroll
                    for (int j = 0; j < 4; j++) {
                        int col = nw + j * 8 + 2 * tig;
                        float v0 = fmaxf((acc[i][j][2*h]   + bcol[j][0] - mu) * rstd * gcol[j][0] + lcol[j][0], 0.f);
                        float v1 = fmaxf((acc[i][j][2*h+1] + bcol[j][1] - mu) * rstd * gcol[j][1] + lcol[j][1], 0.f);
                        float2 o; o.x = v0; o.y = v1;
                        *(float2*)&Cf[(size_t)row * 128 + col] = o;
                        uint2 u; u.x = cvt_tf32(v0); u.y = cvt_tf32(v1);
                        *(uint2*)&C32[(size_t)row * 128 + col] = u;
                    }
                }
            }
        }
    } else {
        float b2col[4][2];
        if constexpr (MODE == 1) {
            #pragma unroll
            for (int j = 0; j < 4; j++) {
                int col = nw + j * 8 + 2 * tig;
                b2col[j][0] = bias2[col];
                b2col[j][1] = bias2[col + 1];
            }
        }
        #pragma unroll
        for (int i = 0; i < 2; i++) {
            #pragma unroll
            for (int h = 0; h < 2; h++) {
                int row = m0 + mw + i * 16 + g + 8 * h;
                if (row >= M) continue;
                float gt = (MODE == 1) ? rowgate[row] : 0.f;
                #pragma unroll
                for (int j = 0; j < 4; j++) {
                    int col = nw + j * 8 + 2 * tig;
                    float v0 = acc[i][j][2 * h] + bcol[j][0];
                    float v1 = acc[i][j][2 * h + 1] + bcol[j][1];
                    if constexpr (MODE == 1) {
                        v0 = fmaxf(fmaf(gt, b2col[j][0], v0), 0.f);
                        v1 = fmaxf(fmaf(gt, b2col[j][1], v1), 0.f);
                        uint2 u; u.x = cvt_tf32(v0); u.y = cvt_tf32(v1);
                        *(uint2*)&C32[(size_t)row * 128 + col] = u;
                    } else {
                        if (blockIdx.y == 0) {
                            float2 o; o.x = v0; o.y = v1;
                            *(float2*)&Cf[(size_t)row * 128 + col] = o;
                        } else {
                            *(__half2*)&Ch[(size_t)row * 128 + col] = __floats2half2_rn(v0, v1);
                        }
                    }
                }
            }
        }
    }
}

// ================= edge aggregation: warp per node, fp16 Q gather =================
// H32[n] = tf32( inv_deg[n] * sum relu(P[n] + Q[src] + ea*w1c) )
__global__ void __launch_bounds__(256) k_aggr(const float* __restrict__ w1c, int N) {
    int warp = (blockIdx.x * blockDim.x + threadIdx.x) >> 5;
    int lane = threadIdx.x & 31;
    if (warp >= N) return;
    int node = warp;
    float4 p = *(const float4*)&g_p[(size_t)node * 128 + lane * 4];
    float4 w = *(const float4*)&w1c[lane * 4];
    float4 acc = make_float4(0.f, 0.f, 0.f, 0.f);
    int s0 = g_rowptr[node], s1 = g_rowptr[node + 1];
    for (int j = s0; j < s1; j++) {
        int src  = g_esrc[j];
        float ea = g_eea[j];
        uint2 raw = *(const uint2*)&g_qh[(size_t)src * 128 + lane * 4];
        float2 q0 = __half22float2(*(const __half2*)&raw.x);
        float2 q1 = __half22float2(*(const __half2*)&raw.y);
        acc.x += fmaxf(fmaf(ea, w.x, p.x + q0.x), 0.0f);
        acc.y += fmaxf(fmaf(ea, w.y, p.y + q0.y), 0.0f);
        acc.z += fmaxf(fmaf(ea, w.z, p.z + q1.x), 0.0f);
        acc.w += fmaxf(fmaf(ea, w.w, p.w + q1.y), 0.0f);
    }
    float inv = g_invdeg[node];
    uint4 u;
    u.x = cvt_tf32(acc.x * inv); u.y = cvt_tf32(acc.y * inv);
    u.z = cvt_tf32(acc.z * inv); u.w = cvt_tf32(acc.w * inv);
    *(uint4*)&g_H32[(size_t)node * 128 + lane * 4] = u;
}

// ================= readout =================
__global__ void k_zero_gvec() { if (threadIdx.x < 128) g_gvec[threadIdx.x] = 0.0f; }
__global__ void k_mean(int N) {
    int c = threadIdx.x;
    int rows_per = (N + gridDim.x - 1) / gridDim.x;
    int r0 = blockIdx.x * rows_per;
    int r1 = min(r0 + rows_per, N);
    float s = 0.0f;
    for (int r = r0; r < r1; r++) s += g_x[(size_t)r * 128 + c];
    atomicAdd(&g_gvec[c], s);
}
__global__ void k_out(const float* __restrict__ W1, const float* __restrict__ b1,
                      const float* __restrict__ W2, const float* __restrict__ b2,
                      float* __restrict__ out, float invN) {
    __shared__ float gs[128];
    __shared__ float hs[128];
    int c = threadIdx.x;
    gs[c] = g_gvec[c] * invN;
    __syncthreads();
    float a = b1[c];
    #pragma unroll 8
    for (int k = 0; k < 128; k++) a = fmaf(gs[k], W1[k * 128 + c], a);
    hs[c] = fmaxf(a, 0.0f);
    __syncthreads();
    float o = b2[c];
    #pragma unroll 8
    for (int k = 0; k < 128; k++) o = fmaf(hs[k], W2[k * 128 + c], o);
    out[c] = o;
}

// ================= launch =================
extern "C" void kernel_launch(void* const* d_in, const int* in_sizes, int n_in,
                              void* d_out, int out_size) {
    const float* node_feat = (const float*)d_in[0];
    const float* edge_attr = (const float*)d_in[1];
    const float* enc_W  = (const float*)d_in[2];
    const float* enc_b  = (const float*)d_in[3];
    const float* mlp_W1 = (const float*)d_in[4];
    const float* mlp_b1 = (const float*)d_in[5];
    const float* mlp_W2 = (const float*)d_in[6];
    const float* mlp_b2 = (const float*)d_in[7];
    const float* upd_W1 = (const float*)d_in[8];
    const float* upd_b1 = (const float*)d_in[9];
    const float* upd_W2 = (const float*)d_in[10];
    const float* upd_b2 = (const float*)d_in[11];
    const float* ln_g   = (const float*)d_in[12];
    const float* ln_b   = (const float*)d_in[13];
    const float* out_W1 = (const float*)d_in[14];
    const float* out_b1 = (const float*)d_in[15];
    const float* out_W2 = (const float*)d_in[16];
    const float* out_b2 = (const float*)d_in[17];
    const int*   ei     = (const int*)d_in[18];

    const int N = NODES;
    const int E = EDGES;

    float *px, *pp, *pbc, *pgate;
    __half* pqh;
    uint32_t *px32, *pH32, *pt32, *pwT;
    cudaGetSymbolAddress((void**)&px,    g_x);
    cudaGetSymbolAddress((void**)&px32,  g_x32);
    cudaGetSymbolAddress((void**)&pp,    g_p);
    cudaGetSymbolAddress((void**)&pqh,   g_qh);
    cudaGetSymbolAddress((void**)&pH32,  g_H32);
    cudaGetSymbolAddress((void**)&pt32,  g_t32);
    cudaGetSymbolAddress((void**)&pwT,   g_wT);
    cudaGetSymbolAddress((void**)&pbc,   g_bc);
    cudaGetSymbolAddress((void**)&pgate, g_gate);

    cudaFuncSetAttribute(gemm_mma<0>, cudaFuncAttributeMaxDynamicSharedMemorySize, GEMM_SMEM_BYTES);
    cudaFuncSetAttribute(gemm_mma<1>, cudaFuncAttributeMaxDynamicSharedMemorySize, GEMM_SMEM_BYTES);
    cudaFuncSetAttribute(gemm_mma<2>, cudaFuncAttributeMaxDynamicSharedMemorySize, GEMM_SMEM_BYTES);

    // CSR build
    k_detect<<<1, 32>>>(ei);
    k_zero_deg<<<(N + 255) / 256, 256>>>(N);
    k_count<<<(E + 255) / 256, 256>>>(ei, E);
    k_scan1<<<(N + 1023) / 1024, 1024>>>(N);
    k_scan2<<<1, 64>>>((N + 1023) / 1024);
    k_scan3<<<(N + 255) / 256, 256>>>(N);
    k_scatter<<<(E + 255) / 256, 256>>>(ei, edge_attr, E);

    // encoder
    k_encode<<<(N * HID + 255) / 256, 256>>>(node_feat, enc_W, enc_b, N);

    const int gt64 = (N + 63) / 64;   // 782

    for (int l = 0; l < NLAYER; l++) {
        const float* W1l = mlp_W1 + (size_t)l * 257 * 128;
        const float* U1l = upd_W1 + (size_t)l * 256 * 128;
        k_repackT<<<4 * 16384 / 256, 256>>>(W1l, U1l, upd_W2 + (size_t)l * 128 * 128);
        k_fuseW<<<128, 128>>>(mlp_W2 + (size_t)l * 128 * 128, U1l, mlp_b2 + l * 128);

        // P = x @ W1a^T + b1 (fp32) ; Q = x @ W1b^T (fp16)
        gemm_mma<0><<<dim3(gt64, 2), 256, GEMM_SMEM_BYTES>>>(
            px32, nullptr, pwT + 0 * 16384, pwT + 1 * 16384, mlp_b1 + l * 128,
            nullptr, nullptr, nullptr, nullptr, pp, nullptr, pqh, N);

        // Hn[n] = inv_deg * sum relu(P[n] + Q[src] + ea*w1c)  -> tf32 bits
        k_aggr<<<(N + 7) / 8, 256>>>(W1l + 256 * 128, N);

        // t = relu(x @ U1a^T + Hn @ Wc^T + b1 + gate*bc)  -> tf32 bits
        gemm_mma<1><<<gt64, 256, GEMM_SMEM_BYTES>>>(
            px32, pH32, pwT + 2 * 16384, pwT + 4 * 16384, upd_b1 + l * 128,
            pbc, pgate, nullptr, nullptr, nullptr, pt32, nullptr, N);

        // x = relu(LN(t @ U2^T + b2))  -> fp32 + tf32 bits
        gemm_mma<2><<<gt64, 256, GEMM_SMEM_BYTES>>>(
            pt32, nullptr, pwT + 3 * 16384, nullptr, upd_b2 + l * 128,
            nullptr, nullptr, ln_g + l * 128, ln_b + l * 128, px, px32, nullptr, N);
    }

    // readout
    k_zero_gvec<<<1, 128>>>();
    k_mean<<<400, 128>>>(N);
    k_out<<<1, 128>>>(out_W1, out_b1, out_W2, out_b2, (float*)d_out, 1.0f / (float)N);
}

// round 7
// speedup vs baseline: 1.6607x; 1.4596x over previous
#include <cuda_runtime.h>
#include <cuda_fp16.h>
#include <cstdint>

#define NODES 50000
#define EDGES 800000
#define HID   128
#define NLAYER 3

// ---------------- scratch (static device globals; no allocation) ----------------
__device__ __half g_xh [NODES * HID];      // node state, fp16 (GEMM A, readout)
__device__ float  g_p  [NODES * HID];      // P per node (fp32)
__device__ __half g_qh [NODES * HID];      // Q per node (fp16, gathered per edge)
__device__ __half g_Hh [NODES * HID];      // inv_deg * segment_sum(relu_h), fp16
__device__ __half g_th [NODES * HID];      // update hidden, fp16
__device__ int   g_esrc[EDGES];
__device__ float g_eea [EDGES];
__device__ int   g_deg [NODES];
__device__ int   g_tmp [NODES];
__device__ int   g_rowptr[NODES + 1];
__device__ int   g_cursor[NODES];
__device__ float g_invdeg[NODES];
__device__ float g_gate  [NODES];
__device__ __half g_wTh[NLAYER * 5 * HID * HID];  // B^T fp16: slots 0=W1a 1=W1b 2=U1a 3=U2 4=Wc
__device__ float g_bc  [NLAYER * HID];            // b2 @ U1b per layer
__device__ float g_gvec[HID];
__device__ int   g_is64;
__device__ int   g_bsum[64];
__device__ int   g_boff[64];

// ================= helpers =================
__device__ __forceinline__ void mma16(float* c, const uint32_t* a, const uint32_t* b) {
    asm volatile(
        "mma.sync.aligned.m16n8k16.row.col.f32.f16.f16.f32 "
        "{%0,%1,%2,%3},{%4,%5,%6,%7},{%8,%9},{%0,%1,%2,%3};"
        : "+f"(c[0]), "+f"(c[1]), "+f"(c[2]), "+f"(c[3])
        : "r"(a[0]), "r"(a[1]), "r"(a[2]), "r"(a[3]), "r"(b[0]), "r"(b[1]));
}

// ================= CSR build =================
__global__ void k_init(const int* __restrict__ ei, int N) {
    int i = blockIdx.x * blockDim.x + threadIdx.x;
    if (i < N) g_deg[i] = 0;
    if (i == 0) {
        int z = 1;
        #pragma unroll
        for (int k = 1; k < 16; k += 2) if (ei[k] != 0) z = 0;
        g_is64 = z;
    }
}
__global__ void k_count(const int* __restrict__ ei, int E) {
    int e = blockIdx.x * blockDim.x + threadIdx.x;
    if (e >= E) return;
    int is64 = g_is64;
    int dst = is64 ? ei[2 * E + 2 * e] : ei[E + e];
    atomicAdd(&g_deg[dst], 1);
}
__global__ void k_scan1(int N) {
    __shared__ int s[1024];
    int tid = threadIdx.x;
    int i = blockIdx.x * 1024 + tid;
    int v = (i < N) ? g_deg[i] : 0;
    s[tid] = v;
    __syncthreads();
    for (int off = 1; off < 1024; off <<= 1) {
        int t = (tid >= off) ? s[tid - off] : 0;
        __syncthreads();
        s[tid] += t;
        __syncthreads();
    }
    if (i < N) g_tmp[i] = s[tid];
    if (tid == 1023) g_bsum[blockIdx.x] = s[1023];
}
__global__ void k_scan2(int nb) {
    __shared__ int s[64];
    int tid = threadIdx.x;
    int v = (tid < nb) ? g_bsum[tid] : 0;
    s[tid] = v;
    __syncthreads();
    for (int off = 1; off < 64; off <<= 1) {
        int t = (tid >= off) ? s[tid - off] : 0;
        __syncthreads();
        s[tid] += t;
        __syncthreads();
    }
    g_boff[tid] = s[tid] - v;   // exclusive
}
__global__ void k_scan3(int N) {
    int i = blockIdx.x * blockDim.x + threadIdx.x;
    if (i >= N) return;
    int incl = g_tmp[i] + g_boff[i >> 10];
    int d = g_deg[i];
    int excl = incl - d;
    g_rowptr[i] = excl;
    g_cursor[i] = excl;
    g_invdeg[i] = 1.0f / fmaxf((float)d, 1.0f);
    g_gate[i]   = (d > 0) ? 1.0f : 0.0f;
    if (i == N - 1) g_rowptr[N] = incl;
}
__global__ void k_scatter(const int* __restrict__ ei, const float* __restrict__ ea, int E) {
    int e = blockIdx.x * blockDim.x + threadIdx.x;
    if (e >= E) return;
    int is64 = g_is64;
    int src = is64 ? ei[2 * e]         : ei[e];
    int dst = is64 ? ei[2 * E + 2 * e] : ei[E + e];
    int pos = atomicAdd(&g_cursor[dst], 1);
    g_esrc[pos] = src;
    g_eea[pos]  = ea[e];
}

// ================= encoder =================
__global__ void k_encode(const float* __restrict__ nf, const float* __restrict__ W,
                         const float* __restrict__ b, int N) {
    int t = blockIdx.x * blockDim.x + threadIdx.x;
    if (t >= N * HID) return;
    int n = t >> 7, c = t & 127;
    float acc = b[c];
    #pragma unroll
    for (int k = 0; k < 5; k++) acc = fmaf(nf[n * 5 + k], W[k * HID + c], acc);
    g_xh[t] = __float2half_rn(acc);
}

// ================= weight repack (ALL layers, transpose, to fp16) =================
// per layer slots: 0=W1a, 1=W1b, 2=U1a, 3=U2
__global__ void k_repackT(const float* __restrict__ mlp_W1, const float* __restrict__ upd_W1,
                          const float* __restrict__ upd_W2) {
    int t = blockIdx.x * blockDim.x + threadIdx.x;   // < NLAYER*4*16384
    int l = t / (4 * 16384);
    int r = t % (4 * 16384);
    int w = r >> 14;
    int j = (r >> 7) & 127;
    int k = r & 127;
    const float* W1 = mlp_W1 + (size_t)l * 257 * 128;
    const float* U1 = upd_W1 + (size_t)l * 256 * 128;
    const float* U2 = upd_W2 + (size_t)l * 128 * 128;
    float v;
    switch (w) {
        case 0:  v = W1[k * 128 + j];          break;
        case 1:  v = W1[(128 + k) * 128 + j];  break;
        case 2:  v = U1[k * 128 + j];          break;
        default: v = U2[k * 128 + j];          break;
    }
    g_wTh[(size_t)l * 5 * 16384 + (size_t)w * 16384 + j * 128 + k] = __float2half_rn(v);
}

// ================= fused small weight: Wc = W2 @ U1b, bc = b2 @ U1b (all layers) =================
__global__ void k_fuseW(const float* __restrict__ mlp_W2, const float* __restrict__ upd_W1,
                        const float* __restrict__ mlp_b2) {
    __shared__ float w2row[128];
    int k = blockIdx.x, l = blockIdx.y, j = threadIdx.x;
    const float* W2 = mlp_W2 + (size_t)l * 128 * 128;
    const float* U1 = upd_W1 + (size_t)l * 256 * 128;
    const float* b2 = mlp_b2 + l * 128;
    w2row[j] = W2[k * 128 + j];
    __syncthreads();
    float acc = 0.f;
    #pragma unroll 8
    for (int t = 0; t < 128; t++) acc = fmaf(w2row[t], U1[(128 + t) * 128 + j], acc);
    g_wTh[(size_t)l * 5 * 16384 + 4 * 16384 + j * 128 + k] = __float2half_rn(acc);
    if (k == 0) {
        float bacc = 0.f;
        #pragma unroll 8
        for (int t = 0; t < 128; t++) bacc = fmaf(b2[t], U1[(128 + t) * 128 + j], bacc);
        g_bc[l * 128 + j] = bacc;
    }
}

// ================= fp16 mma.sync GEMM: 64x128 CTA tile, K=128 =================
// 256 threads = 8 warps (2m x 4n); warp tile 32x32; mma m16n8k16; K chunks of 64.
// 27.6 KB smem, 3 CTAs/SM.
// MODE 0 (PQ):  y=0 -> P = A@W1a^T + b1 (fp32 g_p); y=1 -> Q = A@W1b^T (fp16 g_qh)
// MODE 1 (UPD): dual pass xh@U1a + Hh@Wc; relu(v + bias + rowgate*bias2) -> fp16
// MODE 2 (LN):  relu(LN(v + bias)*lng + lnb) -> fp16
#define STR 72
#define GEMM_SMEM_BYTES ((64 + 128) * STR * 2)

template<int MODE>
__global__ void __launch_bounds__(256, 3)
gemm_mma(const __half* __restrict__ A1, const __half* __restrict__ A2,
         const __half* __restrict__ B1, const __half* __restrict__ B2,
         const float* __restrict__ bias, const float* __restrict__ bias2,
         const float* __restrict__ rowgate,
         const float* __restrict__ lng, const float* __restrict__ lnb,
         float* __restrict__ Cf, __half* __restrict__ Ch, int M)
{
    extern __shared__ __half smh[];
    __half* As = smh;                 // [64][72]
    __half* Bs = smh + 64 * STR;      // [128][72]

    const int tid = threadIdx.x;
    const int wid = tid >> 5, lane = tid & 31;
    const int g = lane >> 2, tig = lane & 3;
    const int warp_m = wid >> 2, warp_n = wid & 3;
    const int mw = warp_m * 32, nw = warp_n * 32;
    const int m0 = blockIdx.x * 64;

    float acc[2][4][4];
    #pragma unroll
    for (int i = 0; i < 2; i++)
        #pragma unroll
        for (int j = 0; j < 4; j++)
            #pragma unroll
            for (int r = 0; r < 4; r++) acc[i][j][r] = 0.0f;

    const int npass = (MODE == 1) ? 2 : 1;
    for (int p = 0; p < npass; p++) {
        const __half* A = (MODE == 1 && p) ? A2 : A1;
        const __half* B;
        if constexpr (MODE == 0) B = (blockIdx.y == 0) ? B1 : B2;
        else                     B = (MODE == 1 && p) ? B2 : B1;
        for (int c = 0; c < 2; c++) {
            __syncthreads();
            // A tile: 64 rows x 8 uint4 (64 halves)
            #pragma unroll
            for (int u = 0; u < 2; u++) {
                int linear = u * 256 + tid;          // 0..511
                int row = linear >> 3;
                int q   = linear & 7;
                uint4 av = make_uint4(0u, 0u, 0u, 0u);
                if (m0 + row < M)
                    av = *(const uint4*)&A[(size_t)(m0 + row) * 128 + c * 64 + q * 8];
                *(uint4*)&As[row * STR + q * 8] = av;
            }
            // B chunk: 128 rows x 8 uint4
            #pragma unroll
            for (int u = 0; u < 4; u++) {
                int linear = u * 256 + tid;          // 0..1023
                int row = linear >> 3;
                int q   = linear & 7;
                *(uint4*)&Bs[row * STR + q * 8] =
                    *(const uint4*)&B[(size_t)row * 128 + c * 64 + q * 8];
            }
            __syncthreads();
            #pragma unroll
            for (int ks = 0; ks < 4; ks++) {
                const int k0 = ks * 16;
                uint32_t af[2][4], bf[4][2];
                #pragma unroll
                for (int i = 0; i < 2; i++) {
                    const __half* r0 = &As[(mw + i * 16 + g) * STR + k0 + 2 * tig];
                    const __half* r1 = r0 + 8 * STR;
                    af[i][0] = *(const uint32_t*)r0;
                    af[i][1] = *(const uint32_t*)r1;
                    af[i][2] = *(const uint32_t*)(r0 + 8);
                    af[i][3] = *(const uint32_t*)(r1 + 8);
                }
                #pragma unroll
                for (int j = 0; j < 4; j++) {
                    const __half* rb = &Bs[(nw + j * 8 + g) * STR + k0 + 2 * tig];
                    bf[j][0] = *(const uint32_t*)rb;
                    bf[j][1] = *(const uint32_t*)(rb + 8);
                }
                #pragma unroll
                for (int i = 0; i < 2; i++)
                    #pragma unroll
                    for (int j = 0; j < 4; j++)
                        mma16(acc[i][j], af[i], bf[j]);
            }
        }
    }

    // ---------------- epilogue ----------------
    float bcol[4][2];
    #pragma unroll
    for (int j = 0; j < 4; j++) {
        int col = nw + j * 8 + 2 * tig;
        bool haveb = (MODE != 0) || (blockIdx.y == 0);
        bcol[j][0] = haveb ? bias[col]     : 0.0f;
        bcol[j][1] = haveb ? bias[col + 1] : 0.0f;
    }

    if constexpr (MODE == 2) {
        __syncthreads();
        float* sS  = (float*)smh;            // [64][4]
        float* sS2 = (float*)smh + 256;
        float gcol[4][2], lcol[4][2];
        #pragma unroll
        for (int j = 0; j < 4; j++) {
            int col = nw + j * 8 + 2 * tig;
            gcol[j][0] = lng[col];     gcol[j][1] = lng[col + 1];
            lcol[j][0] = lnb[col];     lcol[j][1] = lnb[col + 1];
        }
        #pragma unroll
        for (int i = 0; i < 2; i++) {
            #pragma unroll
            for (int h = 0; h < 2; h++) {
                float s = 0.f, s2 = 0.f;
                #pragma unroll
                for (int j = 0; j < 4; j++) {
                    #pragma unroll
                    for (int r = 0; r < 2; r++) {
                        float v = acc[i][j][2 * h + r] + bcol[j][r];
                        s += v; s2 += v * v;
                    }
                }
                s  += __shfl_xor_sync(0xffffffffu, s, 1);
                s  += __shfl_xor_sync(0xffffffffu, s, 2);
                s2 += __shfl_xor_sync(0xffffffffu, s2, 1);
                s2 += __shfl_xor_sync(0xffffffffu, s2, 2);
                if (tig == 0) {
                    int rl = mw + i * 16 + g + 8 * h;
                    sS [rl * 4 + warp_n] = s;
                    sS2[rl * 4 + warp_n] = s2;
                }
            }
        }
        __syncthreads();
        #pragma unroll
        for (int i = 0; i < 2; i++) {
            #pragma unroll
            for (int h = 0; h < 2; h++) {
                int rl = mw + i * 16 + g + 8 * h;
                int row = m0 + rl;
                float s  = sS [rl * 4] + sS [rl * 4 + 1] + sS [rl * 4 + 2] + sS [rl * 4 + 3];
                float s2 = sS2[rl * 4] + sS2[rl * 4 + 1] + sS2[rl * 4 + 2] + sS2[rl * 4 + 3];
                float mu   = s * (1.0f / 128.0f);
                float var  = s2 * (1.0f / 128.0f) - mu * mu;
                float rstd = rsqrtf(var + 1e-5f);
                if (row < M) {
                    #pragma unroll
                    for (int j = 0; j < 4; j++) {
                        int col = nw + j * 8 + 2 * tig;
                        float v0 = fmaxf((acc[i][j][2*h]   + bcol[j][0] - mu) * rstd * gcol[j][0] + lcol[j][0], 0.f);
                        float v1 = fmaxf((acc[i][j][2*h+1] + bcol[j][1] - mu) * rstd * gcol[j][1] + lcol[j][1], 0.f);
                        *(__half2*)&Ch[(size_t)row * 128 + col] = __floats2half2_rn(v0, v1);
                    }
                }
            }
        }
    } else {
        float b2col[4][2];
        if constexpr (MODE == 1) {
            #pragma unroll
            for (int j = 0; j < 4; j++) {
                int col = nw + j * 8 + 2 * tig;
                b2col[j][0] = bias2[col];
                b2col[j][1] = bias2[col + 1];
            }
        }
        #pragma unroll
        for (int i = 0; i < 2; i++) {
            #pragma unroll
            for (int h = 0; h < 2; h++) {
                int row = m0 + mw + i * 16 + g + 8 * h;
                if (row >= M) continue;
                float gt = (MODE == 1) ? rowgate[row] : 0.f;
                #pragma unroll
                for (int j = 0; j < 4; j++) {
                    int col = nw + j * 8 + 2 * tig;
                    float v0 = acc[i][j][2 * h] + bcol[j][0];
                    float v1 = acc[i][j][2 * h + 1] + bcol[j][1];
                    if constexpr (MODE == 1) {
                        v0 = fmaxf(fmaf(gt, b2col[j][0], v0), 0.f);
                        v1 = fmaxf(fmaf(gt, b2col[j][1], v1), 0.f);
                        *(__half2*)&Ch[(size_t)row * 128 + col] = __floats2half2_rn(v0, v1);
                    } else {
                        if (blockIdx.y == 0) {
                            float2 o; o.x = v0; o.y = v1;
                            *(float2*)&Cf[(size_t)row * 128 + col] = o;
                        } else {
                            *(__half2*)&Ch[(size_t)row * 128 + col] = __floats2half2_rn(v0, v1);
                        }
                    }
                }
            }
        }
    }
}

// ================= edge aggregation: warp per node, fp16 Q gather, 2x unroll =================
// Hh[n] = half( inv_deg[n] * sum relu(P[n] + Q[src] + ea*w1c) )
__global__ void __launch_bounds__(256) k_aggr(const float* __restrict__ w1c, int N) {
    int warp = (blockIdx.x * blockDim.x + threadIdx.x) >> 5;
    int lane = threadIdx.x & 31;
    if (warp >= N) return;
    int node = warp;
    float4 p = *(const float4*)&g_p[(size_t)node * 128 + lane * 4];
    float4 w = *(const float4*)&w1c[lane * 4];
    float4 acc = make_float4(0.f, 0.f, 0.f, 0.f);
    int s0 = g_rowptr[node], s1 = g_rowptr[node + 1];
    int j = s0;
    for (; j + 1 < s1; j += 2) {
        int   sa = g_esrc[j],     sb = g_esrc[j + 1];
        float ea = g_eea[j],      eb = g_eea[j + 1];
        uint2 ra = *(const uint2*)&g_qh[(size_t)sa * 128 + lane * 4];
        uint2 rb = *(const uint2*)&g_qh[(size_t)sb * 128 + lane * 4];
        float2 a0 = __half22float2(*(const __half2*)&ra.x);
        float2 a1 = __half22float2(*(const __half2*)&ra.y);
        float2 b0 = __half22float2(*(const __half2*)&rb.x);
        float2 b1 = __half22float2(*(const __half2*)&rb.y);
        acc.x += fmaxf(fmaf(ea, w.x, p.x + a0.x), 0.0f) + fmaxf(fmaf(eb, w.x, p.x + b0.x), 0.0f);
        acc.y += fmaxf(fmaf(ea, w.y, p.y + a0.y), 0.0f) + fmaxf(fmaf(eb, w.y, p.y + b0.y), 0.0f);
        acc.z += fmaxf(fmaf(ea, w.z, p.z + a1.x), 0.0f) + fmaxf(fmaf(eb, w.z, p.z + b1.x), 0.0f);
        acc.w += fmaxf(fmaf(ea, w.w, p.w + a1.y), 0.0f) + fmaxf(fmaf(eb, w.w, p.w + b1.y), 0.0f);
    }
    if (j < s1) {
        int   sa = g_esrc[j];
        float ea = g_eea[j];
        uint2 ra = *(const uint2*)&g_qh[(size_t)sa * 128 + lane * 4];
        float2 a0 = __half22float2(*(const __half2*)&ra.x);
        float2 a1 = __half22float2(*(const __half2*)&ra.y);
        acc.x += fmaxf(fmaf(ea, w.x, p.x + a0.x), 0.0f);
        acc.y += fmaxf(fmaf(ea, w.y, p.y + a0.y), 0.0f);
        acc.z += fmaxf(fmaf(ea, w.z, p.z + a1.x), 0.0f);
        acc.w += fmaxf(fmaf(ea, w.w, p.w + a1.y), 0.0f);
    }
    float inv = g_invdeg[node];
    __half2 h0 = __floats2half2_rn(acc.x * inv, acc.y * inv);
    __half2 h1 = __floats2half2_rn(acc.z * inv, acc.w * inv);
    uint2 u; u.x = *(uint32_t*)&h0; u.y = *(uint32_t*)&h1;
    *(uint2*)&g_Hh[(size_t)node * 128 + lane * 4] = u;
}

// ================= readout =================
__global__ void k_zero_gvec() { if (threadIdx.x < 128) g_gvec[threadIdx.x] = 0.0f; }
__global__ void k_mean(int N) {
    int c = threadIdx.x;
    int rows_per = (N + gridDim.x - 1) / gridDim.x;
    int r0 = blockIdx.x * rows_per;
    int r1 = min(r0 + rows_per, N);
    float s = 0.0f;
    for (int r = r0; r < r1; r++) s += __half2float(g_xh[(size_t)r * 128 + c]);
    atomicAdd(&g_gvec[c], s);
}
__global__ void k_out(const float* __restrict__ W1, const float* __restrict__ b1,
                      const float* __restrict__ W2, const float* __restrict__ b2,
                      float* __restrict__ out, float invN) {
    __shared__ float gs[128];
    __shared__ float hs[128];
    int c = threadIdx.x;
    gs[c] = g_gvec[c] * invN;
    __syncthreads();
    float a = b1[c];
    #pragma unroll 8
    for (int k = 0; k < 128; k++) a = fmaf(gs[k], W1[k * 128 + c], a);
    hs[c] = fmaxf(a, 0.0f);
    __syncthreads();
    float o = b2[c];
    #pragma unroll 8
    for (int k = 0; k < 128; k++) o = fmaf(hs[k], W2[k * 128 + c], o);
    out[c] = o;
}

// ================= launch =================
extern "C" void kernel_launch(void* const* d_in, const int* in_sizes, int n_in,
                              void* d_out, int out_size) {
    const float* node_feat = (const float*)d_in[0];
    const float* edge_attr = (const float*)d_in[1];
    const float* enc_W  = (const float*)d_in[2];
    const float* enc_b  = (const float*)d_in[3];
    const float* mlp_W1 = (const float*)d_in[4];
    const float* mlp_b1 = (const float*)d_in[5];
    const float* mlp_W2 = (const float*)d_in[6];
    const float* mlp_b2 = (const float*)d_in[7];
    const float* upd_W1 = (const float*)d_in[8];
    const float* upd_b1 = (const float*)d_in[9];
    const float* upd_W2 = (const float*)d_in[10];
    const float* upd_b2 = (const float*)d_in[11];
    const float* ln_g   = (const float*)d_in[12];
    const float* ln_b   = (const float*)d_in[13];
    const float* out_W1 = (const float*)d_in[14];
    const float* out_b1 = (const float*)d_in[15];
    const float* out_W2 = (const float*)d_in[16];
    const float* out_b2 = (const float*)d_in[17];
    const int*   ei     = (const int*)d_in[18];

    const int N = NODES;
    const int E = EDGES;

    float *pp, *pbc, *pgate;
    __half *pxh, *pqh, *pHh, *pth, *pwTh;
    cudaGetSymbolAddress((void**)&pxh,   g_xh);
    cudaGetSymbolAddress((void**)&pp,    g_p);
    cudaGetSymbolAddress((void**)&pqh,   g_qh);
    cudaGetSymbolAddress((void**)&pHh,   g_Hh);
    cudaGetSymbolAddress((void**)&pth,   g_th);
    cudaGetSymbolAddress((void**)&pwTh,  g_wTh);
    cudaGetSymbolAddress((void**)&pbc,   g_bc);
    cudaGetSymbolAddress((void**)&pgate, g_gate);

    cudaFuncSetAttribute(gemm_mma<0>, cudaFuncAttributeMaxDynamicSharedMemorySize, GEMM_SMEM_BYTES);
    cudaFuncSetAttribute(gemm_mma<1>, cudaFuncAttributeMaxDynamicSharedMemorySize, GEMM_SMEM_BYTES);
    cudaFuncSetAttribute(gemm_mma<2>, cudaFuncAttributeMaxDynamicSharedMemorySize, GEMM_SMEM_BYTES);

    // CSR build
    k_init<<<(N + 255) / 256, 256>>>(ei, N);
    k_count<<<(E + 255) / 256, 256>>>(ei, E);
    k_scan1<<<(N + 1023) / 1024, 1024>>>(N);
    k_scan2<<<1, 64>>>((N + 1023) / 1024);
    k_scan3<<<(N + 255) / 256, 256>>>(N);
    k_scatter<<<(E + 255) / 256, 256>>>(ei, edge_attr, E);

    // encoder + weight prep (all layers)
    k_encode<<<(N * HID + 255) / 256, 256>>>(node_feat, enc_W, enc_b, N);
    k_repackT<<<NLAYER * 4 * 16384 / 256, 256>>>(mlp_W1, upd_W1, upd_W2);
    k_fuseW<<<dim3(128, NLAYER), 128>>>(mlp_W2, upd_W1, mlp_b2);

    const int gt64 = (N + 63) / 64;   // 782

    for (int l = 0; l < NLAYER; l++) {
        const float* W1l = mlp_W1 + (size_t)l * 257 * 128;
        __half* wl = pwTh + (size_t)l * 5 * 16384;

        // P = x @ W1a^T + b1 (fp32) ; Q = x @ W1b^T (fp16)
        gemm_mma<0><<<dim3(gt64, 2), 256, GEMM_SMEM_BYTES>>>(
            pxh, nullptr, wl + 0 * 16384, wl + 1 * 16384, mlp_b1 + l * 128,
            nullptr, nullptr, nullptr, nullptr, pp, pqh, N);

        // Hh[n] = inv_deg * sum relu(P[n] + Q[src] + ea*w1c)
        k_aggr<<<(N + 7) / 8, 256>>>(W1l + 256 * 128, N);

        // t = relu(x @ U1a^T + Hh @ Wc^T + b1 + gate*bc)
        gemm_mma<1><<<gt64, 256, GEMM_SMEM_BYTES>>>(
            pxh, pHh, wl + 2 * 16384, wl + 4 * 16384, upd_b1 + l * 128,
            pbc + l * 128, pgate, nullptr, nullptr, nullptr, pth, N);

        // x = relu(LN(t @ U2^T + b2))
        gemm_mma<2><<<gt64, 256, GEMM_SMEM_BYTES>>>(
            pth, nullptr, wl + 3 * 16384, nullptr, upd_b2 + l * 128,
            nullptr, nullptr, ln_g + l * 128, ln_b + l * 128, nullptr, pxh, N);
    }

    // readout
    k_zero_gvec<<<1, 128>>>();
    k_mean<<<400, 128>>>(N);
    k_out<<<1, 128>>>(out_W1, out_b1, out_W2, out_b2, (float*)d_out, 1.0f / (float)N);
}

// round 8
// speedup vs baseline: 1.7712x; 1.0666x over previous
#include <cuda_runtime.h>
#include <cuda_fp16.h>
#include <cstdint>

#define NODES 50000
#define EDGES 800000
#define HID   128
#define NLAYER 3

// ---------------- scratch (static device globals; no allocation) ----------------
__device__ __half g_xh [NODES * HID];      // node state, fp16 (GEMM A, readout, in-place update)
__device__ float  g_p  [NODES * HID];      // P per node (fp32)
__device__ __half g_qh [NODES * HID];      // Q per node (fp16, gathered per edge)
__device__ __half g_Hh [NODES * HID];      // inv_deg * segment_sum(relu_h), fp16
__device__ int2  g_edge[EDGES];            // {src, ea bits} packed
__device__ int   g_deg [NODES];
__device__ int   g_tmp [NODES];
__device__ int   g_rowptr[NODES + 1];
__device__ int   g_cursor[NODES];
__device__ float g_invdeg[NODES];
__device__ float g_gate  [NODES];
__device__ __half g_wTh[NLAYER * 5 * HID * HID];  // B^T fp16: 0=W1a 1=W1b 2=U1a 3=U2 4=Wc
__device__ float g_bc  [NLAYER * HID];            // b2 @ U1b per layer
__device__ float g_gvec[HID];
__device__ int   g_is64;
__device__ int   g_bsum[64];
__device__ int   g_boff[64];

// ================= helpers =================
__device__ __forceinline__ void mma16(float* c, const uint32_t* a, const uint32_t* b) {
    asm volatile(
        "mma.sync.aligned.m16n8k16.row.col.f32.f16.f16.f32 "
        "{%0,%1,%2,%3},{%4,%5,%6,%7},{%8,%9},{%0,%1,%2,%3};"
        : "+f"(c[0]), "+f"(c[1]), "+f"(c[2]), "+f"(c[3])
        : "r"(a[0]), "r"(a[1]), "r"(a[2]), "r"(a[3]), "r"(b[0]), "r"(b[1]));
}

// ================= CSR build =================
__global__ void k_init(const int* __restrict__ ei, int N) {
    int i = blockIdx.x * blockDim.x + threadIdx.x;
    if (i < N) g_deg[i] = 0;
    if (i == 0) {
        int z = 1;
        #pragma unroll
        for (int k = 1; k < 16; k += 2) if (ei[k] != 0) z = 0;
        g_is64 = z;
    }
}
__global__ void k_count(const int* __restrict__ ei, int E) {
    int e = blockIdx.x * blockDim.x + threadIdx.x;
    if (e >= E) return;
    int is64 = g_is64;
    int dst = is64 ? ei[2 * E + 2 * e] : ei[E + e];
    atomicAdd(&g_deg[dst], 1);
}
__global__ void k_scan1(int N) {
    __shared__ int s[1024];
    int tid = threadIdx.x;
    int i = blockIdx.x * 1024 + tid;
    int v = (i < N) ? g_deg[i] : 0;
    s[tid] = v;
    __syncthreads();
    for (int off = 1; off < 1024; off <<= 1) {
        int t = (tid >= off) ? s[tid - off] : 0;
        __syncthreads();
        s[tid] += t;
        __syncthreads();
    }
    if (i < N) g_tmp[i] = s[tid];
    if (tid == 1023) g_bsum[blockIdx.x] = s[1023];
}
__global__ void k_scan2(int nb) {
    __shared__ int s[64];
    int tid = threadIdx.x;
    int v = (tid < nb) ? g_bsum[tid] : 0;
    s[tid] = v;
    __syncthreads();
    for (int off = 1; off < 64; off <<= 1) {
        int t = (tid >= off) ? s[tid - off] : 0;
        __syncthreads();
        s[tid] += t;
        __syncthreads();
    }
    g_boff[tid] = s[tid] - v;   // exclusive
}
__global__ void k_scan3(int N) {
    int i = blockIdx.x * blockDim.x + threadIdx.x;
    if (i >= N) return;
    int incl = g_tmp[i] + g_boff[i >> 10];
    int d = g_deg[i];
    int excl = incl - d;
    g_rowptr[i] = excl;
    g_cursor[i] = excl;
    g_invdeg[i] = 1.0f / fmaxf((float)d, 1.0f);
    g_gate[i]   = (d > 0) ? 1.0f : 0.0f;
    if (i == N - 1) g_rowptr[N] = incl;
}
__global__ void k_scatter(const int* __restrict__ ei, const float* __restrict__ ea, int E) {
    int e = blockIdx.x * blockDim.x + threadIdx.x;
    if (e >= E) return;
    int is64 = g_is64;
    int src = is64 ? ei[2 * e]         : ei[e];
    int dst = is64 ? ei[2 * E + 2 * e] : ei[E + e];
    int pos = atomicAdd(&g_cursor[dst], 1);
    g_edge[pos] = make_int2(src, __float_as_int(ea[e]));
}

// ================= encoder =================
__global__ void k_encode(const float* __restrict__ nf, const float* __restrict__ W,
                         const float* __restrict__ b, int N) {
    int t = blockIdx.x * blockDim.x + threadIdx.x;
    if (t >= N * HID) return;
    int n = t >> 7, c = t & 127;
    float acc = b[c];
    #pragma unroll
    for (int k = 0; k < 5; k++) acc = fmaf(nf[n * 5 + k], W[k * HID + c], acc);
    g_xh[t] = __float2half_rn(acc);
}

// ================= weight repack (ALL layers, transpose, to fp16) =================
__global__ void k_repackT(const float* __restrict__ mlp_W1, const float* __restrict__ upd_W1,
                          const float* __restrict__ upd_W2) {
    int t = blockIdx.x * blockDim.x + threadIdx.x;   // < NLAYER*4*16384
    int l = t / (4 * 16384);
    int r = t % (4 * 16384);
    int w = r >> 14;
    int j = (r >> 7) & 127;
    int k = r & 127;
    const float* W1 = mlp_W1 + (size_t)l * 257 * 128;
    const float* U1 = upd_W1 + (size_t)l * 256 * 128;
    const float* U2 = upd_W2 + (size_t)l * 128 * 128;
    float v;
    switch (w) {
        case 0:  v = W1[k * 128 + j];          break;
        case 1:  v = W1[(128 + k) * 128 + j];  break;
        case 2:  v = U1[k * 128 + j];          break;
        default: v = U2[k * 128 + j];          break;
    }
    g_wTh[(size_t)l * 5 * 16384 + (size_t)w * 16384 + j * 128 + k] = __float2half_rn(v);
}

// ================= fused small weight: Wc = W2 @ U1b, bc = b2 @ U1b (all layers) =================
__global__ void k_fuseW(const float* __restrict__ mlp_W2, const float* __restrict__ upd_W1,
                        const float* __restrict__ mlp_b2) {
    __shared__ float w2row[128];
    int k = blockIdx.x, l = blockIdx.y, j = threadIdx.x;
    const float* W2 = mlp_W2 + (size_t)l * 128 * 128;
    const float* U1 = upd_W1 + (size_t)l * 256 * 128;
    const float* b2 = mlp_b2 + l * 128;
    w2row[j] = W2[k * 128 + j];
    __syncthreads();
    float acc = 0.f;
    #pragma unroll 8
    for (int t = 0; t < 128; t++) acc = fmaf(w2row[t], U1[(128 + t) * 128 + j], acc);
    g_wTh[(size_t)l * 5 * 16384 + 4 * 16384 + j * 128 + k] = __float2half_rn(acc);
    if (k == 0) {
        float bacc = 0.f;
        #pragma unroll 8
        for (int t = 0; t < 128; t++) bacc = fmaf(b2[t], U1[(128 + t) * 128 + j], bacc);
        g_bc[l * 128 + j] = bacc;
    }
}

// ================= fp16 mma.sync GEMM kernels =================
// 64x128 CTA tile, 256 threads = 8 warps (2m x 4n), warp tile 32x32, mma m16n8k16.
#define STR  72
#define STRT 136
#define PQ_SMEM_BYTES   ((64 + 128) * STR * 2)
#define UPD_SMEM_BYTES  (((64 + 128) * STR + 64 * STRT) * 2)

// ---- shared mainloop piece: fill Bs chunk + compute over 64-wide K chunk ----
// (written inline in each kernel; helpers for fragment math)

// ================= PQ kernel =================
// y=0: P = x @ W1a^T + b1 (fp32 g_p);  y=1: Q = x @ W1b^T (fp16 g_qh)
__global__ void __launch_bounds__(256, 3)
k_gemm_pq(const __half* __restrict__ A1,
          const __half* __restrict__ B1, const __half* __restrict__ B2,
          const float* __restrict__ bias,
          float* __restrict__ Cf, __half* __restrict__ Ch, int M)
{
    extern __shared__ __half smh[];
    __half* As = smh;                 // [64][72]
    __half* Bs = smh + 64 * STR;      // [128][72]

    const int tid = threadIdx.x;
    const int wid = tid >> 5, lane = tid & 31;
    const int g = lane >> 2, tig = lane & 3;
    const int warp_m = wid >> 2, warp_n = wid & 3;
    const int mw = warp_m * 32, nw = warp_n * 32;
    const int m0 = blockIdx.x * 64;
    const __half* B = (blockIdx.y == 0) ? B1 : B2;

    float acc[2][4][4];
    #pragma unroll
    for (int i = 0; i < 2; i++)
        #pragma unroll
        for (int j = 0; j < 4; j++)
            #pragma unroll
            for (int r = 0; r < 4; r++) acc[i][j][r] = 0.0f;

    for (int c = 0; c < 2; c++) {
        __syncthreads();
        #pragma unroll
        for (int u = 0; u < 2; u++) {
            int linear = u * 256 + tid;
            int row = linear >> 3, q = linear & 7;
            uint4 av = make_uint4(0u, 0u, 0u, 0u);
            if (m0 + row < M)
                av = *(const uint4*)&A1[(size_t)(m0 + row) * 128 + c * 64 + q * 8];
            *(uint4*)&As[row * STR + q * 8] = av;
        }
        #pragma unroll
        for (int u = 0; u < 4; u++) {
            int linear = u * 256 + tid;
            int row = linear >> 3, q = linear & 7;
            *(uint4*)&Bs[row * STR + q * 8] =
                *(const uint4*)&B[(size_t)row * 128 + c * 64 + q * 8];
        }
        __syncthreads();
        #pragma unroll
        for (int ks = 0; ks < 4; ks++) {
            const int k0 = ks * 16;
            uint32_t af[2][4], bf[4][2];
            #pragma unroll
            for (int i = 0; i < 2; i++) {
                const __half* r0 = &As[(mw + i * 16 + g) * STR + k0 + 2 * tig];
                const __half* r1 = r0 + 8 * STR;
                af[i][0] = *(const uint32_t*)r0;
                af[i][1] = *(const uint32_t*)r1;
                af[i][2] = *(const uint32_t*)(r0 + 8);
                af[i][3] = *(const uint32_t*)(r1 + 8);
            }
            #pragma unroll
            for (int j = 0; j < 4; j++) {
                const __half* rb = &Bs[(nw + j * 8 + g) * STR + k0 + 2 * tig];
                bf[j][0] = *(const uint32_t*)rb;
                bf[j][1] = *(const uint32_t*)(rb + 8);
            }
            #pragma unroll
            for (int i = 0; i < 2; i++)
                #pragma unroll
                for (int j = 0; j < 4; j++)
                    mma16(acc[i][j], af[i], bf[j]);
        }
    }

    float bcol[4][2];
    #pragma unroll
    for (int j = 0; j < 4; j++) {
        int col = nw + j * 8 + 2 * tig;
        bool haveb = (blockIdx.y == 0);
        bcol[j][0] = haveb ? bias[col]     : 0.0f;
        bcol[j][1] = haveb ? bias[col + 1] : 0.0f;
    }
    #pragma unroll
    for (int i = 0; i < 2; i++) {
        #pragma unroll
        for (int h = 0; h < 2; h++) {
            int row = m0 + mw + i * 16 + g + 8 * h;
            if (row >= M) continue;
            #pragma unroll
            for (int j = 0; j < 4; j++) {
                int col = nw + j * 8 + 2 * tig;
                float v0 = acc[i][j][2 * h] + bcol[j][0];
                float v1 = acc[i][j][2 * h + 1] + bcol[j][1];
                if (blockIdx.y == 0) {
                    float2 o; o.x = v0; o.y = v1;
                    *(float2*)&Cf[(size_t)row * 128 + col] = o;
                } else {
                    *(__half2*)&Ch[(size_t)row * 128 + col] = __floats2half2_rn(v0, v1);
                }
            }
        }
    }
}

// ================= fused UPD + LN kernel =================
// phase 1: t = relu(x@U1a^T + Hh@Wc^T + b1 + gate*bc)  -> smem T (fp16)
// phase 2: x = relu(LN(t@U2^T + b2)*lng + lnb)          -> g_xh in-place
__global__ void __launch_bounds__(256, 3)
k_gemm_updln(const __half* __restrict__ A1, const __half* __restrict__ A2,
             const __half* __restrict__ B1, const __half* __restrict__ B2,
             const __half* __restrict__ B3,
             const float* __restrict__ bias, const float* __restrict__ bias2,
             const float* __restrict__ rowgate,
             const float* __restrict__ biasln,
             const float* __restrict__ lng, const float* __restrict__ lnb,
             __half* __restrict__ Ch, int M)
{
    extern __shared__ __half smh[];
    __half* As = smh;                        // [64][72]
    __half* Bs = smh + 64 * STR;             // [128][72]
    __half* T  = smh + (64 + 128) * STR;     // [64][136]

    const int tid = threadIdx.x;
    const int wid = tid >> 5, lane = tid & 31;
    const int g = lane >> 2, tig = lane & 3;
    const int warp_m = wid >> 2, warp_n = wid & 3;
    const int mw = warp_m * 32, nw = warp_n * 32;
    const int m0 = blockIdx.x * 64;

    float acc[2][4][4];
    #pragma unroll
    for (int i = 0; i < 2; i++)
        #pragma unroll
        for (int j = 0; j < 4; j++)
            #pragma unroll
            for (int r = 0; r < 4; r++) acc[i][j][r] = 0.0f;

    // ---- phase 1: dual-input GEMM ----
    for (int p = 0; p < 2; p++) {
        const __half* A = p ? A2 : A1;
        const __half* B = p ? B2 : B1;
        for (int c = 0; c < 2; c++) {
            __syncthreads();
            #pragma unroll
            for (int u = 0; u < 2; u++) {
                int linear = u * 256 + tid;
                int row = linear >> 3, q = linear & 7;
                uint4 av = make_uint4(0u, 0u, 0u, 0u);
                if (m0 + row < M)
                    av = *(const uint4*)&A[(size_t)(m0 + row) * 128 + c * 64 + q * 8];
                *(uint4*)&As[row * STR + q * 8] = av;
            }
            #pragma unroll
            for (int u = 0; u < 4; u++) {
                int linear = u * 256 + tid;
                int row = linear >> 3, q = linear & 7;
                *(uint4*)&Bs[row * STR + q * 8] =
                    *(const uint4*)&B[(size_t)row * 128 + c * 64 + q * 8];
            }
            __syncthreads();
            #pragma unroll
            for (int ks = 0; ks < 4; ks++) {
                const int k0 = ks * 16;
                uint32_t af[2][4], bf[4][2];
                #pragma unroll
                for (int i = 0; i < 2; i++) {
                    const __half* r0 = &As[(mw + i * 16 + g) * STR + k0 + 2 * tig];
                    const __half* r1 = r0 + 8 * STR;
                    af[i][0] = *(const uint32_t*)r0;
                    af[i][1] = *(const uint32_t*)r1;
                    af[i][2] = *(const uint32_t*)(r0 + 8);
                    af[i][3] = *(const uint32_t*)(r1 + 8);
                }
                #pragma unroll
                for (int j = 0; j < 4; j++) {
                    const __half* rb = &Bs[(nw + j * 8 + g) * STR + k0 + 2 * tig];
                    bf[j][0] = *(const uint32_t*)rb;
                    bf[j][1] = *(const uint32_t*)(rb + 8);
                }
                #pragma unroll
                for (int i = 0; i < 2; i++)
                    #pragma unroll
                    for (int j = 0; j < 4; j++)
                        mma16(acc[i][j], af[i], bf[j]);
            }
        }
    }

    // ---- epilogue 1: t -> smem T (fp16), then re-zero acc ----
    {
        float bcol[4][2], b2col[4][2];
        #pragma unroll
        for (int j = 0; j < 4; j++) {
            int col = nw + j * 8 + 2 * tig;
            bcol[j][0]  = bias[col];      bcol[j][1]  = bias[col + 1];
            b2col[j][0] = bias2[col];     b2col[j][1] = bias2[col + 1];
        }
        #pragma unroll
        for (int i = 0; i < 2; i++) {
            #pragma unroll
            for (int h = 0; h < 2; h++) {
                int rl = mw + i * 16 + g + 8 * h;
                int row = m0 + rl;
                float gt = (row < M) ? rowgate[row] : 0.f;
                #pragma unroll
                for (int j = 0; j < 4; j++) {
                    int col = nw + j * 8 + 2 * tig;
                    float v0 = fmaxf(acc[i][j][2*h]   + bcol[j][0] + gt * b2col[j][0], 0.f);
                    float v1 = fmaxf(acc[i][j][2*h+1] + bcol[j][1] + gt * b2col[j][1], 0.f);
                    *(__half2*)&T[rl * STRT + col] = __floats2half2_rn(v0, v1);
                }
            }
        }
    }
    #pragma unroll
    for (int i = 0; i < 2; i++)
        #pragma unroll
        for (int j = 0; j < 4; j++)
            #pragma unroll
            for (int r = 0; r < 4; r++) acc[i][j][r] = 0.0f;

    // ---- phase 2: t @ U2^T (A from smem T) ----
    for (int c = 0; c < 2; c++) {
        __syncthreads();   // covers T visibility (c==0) and Bs reuse
        #pragma unroll
        for (int u = 0; u < 4; u++) {
            int linear = u * 256 + tid;
            int row = linear >> 3, q = linear & 7;
            *(uint4*)&Bs[row * STR + q * 8] =
                *(const uint4*)&B3[(size_t)row * 128 + c * 64 + q * 8];
        }
        __syncthreads();
        #pragma unroll
        for (int ks = 0; ks < 4; ks++) {
            const int k0 = c * 64 + ks * 16;
            uint32_t af[2][4], bf[4][2];
            #pragma unroll
            for (int i = 0; i < 2; i++) {
                const __half* r0 = &T[(mw + i * 16 + g) * STRT + k0 + 2 * tig];
                const __half* r1 = r0 + 8 * STRT;
                af[i][0] = *(const uint32_t*)r0;
                af[i][1] = *(const uint32_t*)r1;
                af[i][2] = *(const uint32_t*)(r0 + 8);
                af[i][3] = *(const uint32_t*)(r1 + 8);
            }
            #pragma unroll
            for (int j = 0; j < 4; j++) {
                const __half* rb = &Bs[(nw + j * 8 + g) * STR + (ks * 16) + 2 * tig];
                bf[j][0] = *(const uint32_t*)rb;
                bf[j][1] = *(const uint32_t*)(rb + 8);
            }
            #pragma unroll
            for (int i = 0; i < 2; i++)
                #pragma unroll
                for (int j = 0; j < 4; j++)
                    mma16(acc[i][j], af[i], bf[j]);
        }
    }

    // ---- LN epilogue ----
    {
        __syncthreads();
        float* sS  = (float*)As;            // [64][4]
        float* sS2 = (float*)As + 256;
        float bcol[4][2], gcol[4][2], lcol[4][2];
        #pragma unroll
        for (int j = 0; j < 4; j++) {
            int col = nw + j * 8 + 2 * tig;
            bcol[j][0] = biasln[col];  bcol[j][1] = biasln[col + 1];
            gcol[j][0] = lng[col];     gcol[j][1] = lng[col + 1];
            lcol[j][0] = lnb[col];     lcol[j][1] = lnb[col + 1];
        }
        #pragma unroll
        for (int i = 0; i < 2; i++) {
            #pragma unroll
            for (int h = 0; h < 2; h++) {
                float s = 0.f, s2 = 0.f;
                #pragma unroll
                for (int j = 0; j < 4; j++) {
                    #pragma unroll
                    for (int r = 0; r < 2; r++) {
                        float v = acc[i][j][2 * h + r] + bcol[j][r];
                        s += v; s2 += v * v;
                    }
                }
                s  += __shfl_xor_sync(0xffffffffu, s, 1);
                s  += __shfl_xor_sync(0xffffffffu, s, 2);
                s2 += __shfl_xor_sync(0xffffffffu, s2, 1);
                s2 += __shfl_xor_sync(0xffffffffu, s2, 2);
                if (tig == 0) {
                    int rl = mw + i * 16 + g + 8 * h;
                    sS [rl * 4 + warp_n] = s;
                    sS2[rl * 4 + warp_n] = s2;
                }
            }
        }
        __syncthreads();
        #pragma unroll
        for (int i = 0; i < 2; i++) {
            #pragma unroll
            for (int h = 0; h < 2; h++) {
                int rl = mw + i * 16 + g + 8 * h;
                int row = m0 + rl;
                float s  = sS [rl * 4] + sS [rl * 4 + 1] + sS [rl * 4 + 2] + sS [rl * 4 + 3];
                float s2 = sS2[rl * 4] + sS2[rl * 4 + 1] + sS2[rl * 4 + 2] + sS2[rl * 4 + 3];
                float mu   = s * (1.0f / 128.0f);
                float var  = s2 * (1.0f / 128.0f) - mu * mu;
                float rstd = rsqrtf(var + 1e-5f);
                if (row < M) {
                    #pragma unroll
                    for (int j = 0; j < 4; j++) {
                        int col = nw + j * 8 + 2 * tig;
                        float v0 = fmaxf((acc[i][j][2*h]   + bcol[j][0] - mu) * rstd * gcol[j][0] + lcol[j][0], 0.f);
                        float v1 = fmaxf((acc[i][j][2*h+1] + bcol[j][1] - mu) * rstd * gcol[j][1] + lcol[j][1], 0.f);
                        *(__half2*)&Ch[(size_t)row * 128 + col] = __floats2half2_rn(v0, v1);
                    }
                }
            }
        }
    }
}

// ================= edge aggregation: warp per node, fp16 Q gather, 4x unroll =================
__global__ void __launch_bounds__(256) k_aggr(const float* __restrict__ w1c, int N) {
    int warp = (blockIdx.x * blockDim.x + threadIdx.x) >> 5;
    int lane = threadIdx.x & 31;
    if (warp >= N) return;
    int node = warp;
    float4 p = *(const float4*)&g_p[(size_t)node * 128 + lane * 4];
    float4 w = *(const float4*)&w1c[lane * 4];
    float4 acc = make_float4(0.f, 0.f, 0.f, 0.f);
    int s0 = g_rowptr[node], s1 = g_rowptr[node + 1];
    const int2* ep = g_edge;
    int j = s0;
    for (; j + 3 < s1; j += 4) {
        int2 e0 = __ldg(&ep[j]);
        int2 e1 = __ldg(&ep[j + 1]);
        int2 e2 = __ldg(&ep[j + 2]);
        int2 e3 = __ldg(&ep[j + 3]);
        uint2 r0 = *(const uint2*)&g_qh[(size_t)e0.x * 128 + lane * 4];
        uint2 r1 = *(const uint2*)&g_qh[(size_t)e1.x * 128 + lane * 4];
        uint2 r2 = *(const uint2*)&g_qh[(size_t)e2.x * 128 + lane * 4];
        uint2 r3 = *(const uint2*)&g_qh[(size_t)e3.x * 128 + lane * 4];
        float ea0 = __int_as_float(e0.y), ea1 = __int_as_float(e1.y);
        float ea2 = __int_as_float(e2.y), ea3 = __int_as_float(e3.y);
        float2 a0 = __half22float2(*(const __half2*)&r0.x);
        float2 a1 = __half22float2(*(const __half2*)&r0.y);
        float2 b0 = __half22float2(*(const __half2*)&r1.x);
        float2 b1 = __half22float2(*(const __half2*)&r1.y);
        float2 c0 = __half22float2(*(const __half2*)&r2.x);
        float2 c1 = __half22float2(*(const __half2*)&r2.y);
        float2 d0 = __half22float2(*(const __half2*)&r3.x);
        float2 d1 = __half22float2(*(const __half2*)&r3.y);
        acc.x += fmaxf(fmaf(ea0, w.x, p.x + a0.x), 0.f) + fmaxf(fmaf(ea1, w.x, p.x + b0.x), 0.f)
               + fmaxf(fmaf(ea2, w.x, p.x + c0.x), 0.f) + fmaxf(fmaf(ea3, w.x, p.x + d0.x), 0.f);
        acc.y += fmaxf(fmaf(ea0, w.y, p.y + a0.y), 0.f) + fmaxf(fmaf(ea1, w.y, p.y + b0.y), 0.f)
               + fmaxf(fmaf(ea2, w.y, p.y + c0.y), 0.f) + fmaxf(fmaf(ea3, w.y, p.y + d0.y), 0.f);
        acc.z += fmaxf(fmaf(ea0, w.z, p.z + a1.x), 0.f) + fmaxf(fmaf(ea1, w.z, p.z + b1.x), 0.f)
               + fmaxf(fmaf(ea2, w.z, p.z + c1.x), 0.f) + fmaxf(fmaf(ea3, w.z, p.z + d1.x), 0.f);
        acc.w += fmaxf(fmaf(ea0, w.w, p.w + a1.y), 0.f) + fmaxf(fmaf(ea1, w.w, p.w + b1.y), 0.f)
               + fmaxf(fmaf(ea2, w.w, p.w + c1.y), 0.f) + fmaxf(fmaf(ea3, w.w, p.w + d1.y), 0.f);
    }
    for (; j < s1; j++) {
        int2 e = __ldg(&ep[j]);
        float ea = __int_as_float(e.y);
        uint2 ra = *(const uint2*)&g_qh[(size_t)e.x * 128 + lane * 4];
        float2 a0 = __half22float2(*(const __half2*)&ra.x);
        float2 a1 = __half22float2(*(const __half2*)&ra.y);
        acc.x += fmaxf(fmaf(ea, w.x, p.x + a0.x), 0.f);
        acc.y += fmaxf(fmaf(ea, w.y, p.y + a0.y), 0.f);
        acc.z += fmaxf(fmaf(ea, w.z, p.z + a1.x), 0.f);
        acc.w += fmaxf(fmaf(ea, w.w, p.w + a1.y), 0.f);
    }
    float inv = g_invdeg[node];
    __half2 h0 = __floats2half2_rn(acc.x * inv, acc.y * inv);
    __half2 h1 = __floats2half2_rn(acc.z * inv, acc.w * inv);
    uint2 u; u.x = *(uint32_t*)&h0; u.y = *(uint32_t*)&h1;
    *(uint2*)&g_Hh[(size_t)node * 128 + lane * 4] = u;
}

// ================= readout =================
__global__ void k_zero_gvec() { if (threadIdx.x < 128) g_gvec[threadIdx.x] = 0.0f; }
__global__ void k_mean(int N) {
    int c = threadIdx.x;
    int rows_per = (N + gridDim.x - 1) / gridDim.x;
    int r0 = blockIdx.x * rows_per;
    int r1 = min(r0 + rows_per, N);
    float s = 0.0f;
    for (int r = r0; r < r1; r++) s += __half2float(g_xh[(size_t)r * 128 + c]);
    atomicAdd(&g_gvec[c], s);
}
__global__ void k_out(const float* __restrict__ W1, const float* __restrict__ b1,
                      const float* __restrict__ W2, const float* __restrict__ b2,
                      float* __restrict__ out, float invN) {
    __shared__ float gs[128];
    __shared__ float hs[128];
    int c = threadIdx.x;
    gs[c] = g_gvec[c] * invN;
    __syncthreads();
    float a = b1[c];
    #pragma unroll 8
    for (int k = 0; k < 128; k++) a = fmaf(gs[k], W1[k * 128 + c], a);
    hs[c] = fmaxf(a, 0.0f);
    __syncthreads();
    float o = b2[c];
    #pragma unroll 8
    for (int k = 0; k < 128; k++) o = fmaf(hs[k], W2[k * 128 + c], o);
    out[c] = o;
}

// ================= launch =================
extern "C" void kernel_launch(void* const* d_in, const int* in_sizes, int n_in,
                              void* d_out, int out_size) {
    const float* node_feat = (const float*)d_in[0];
    const float* edge_attr = (const float*)d_in[1];
    const float* enc_W  = (const float*)d_in[2];
    const float* enc_b  = (const float*)d_in[3];
    const float* mlp_W1 = (const float*)d_in[4];
    const float* mlp_b1 = (const float*)d_in[5];
    const float* mlp_W2 = (const float*)d_in[6];
    const float* mlp_b2 = (const float*)d_in[7];
    const float* upd_W1 = (const float*)d_in[8];
    const float* upd_b1 = (const float*)d_in[9];
    const float* upd_W2 = (const float*)d_in[10];
    const float* upd_b2 = (const float*)d_in[11];
    const float* ln_g   = (const float*)d_in[12];
    const float* ln_b   = (const float*)d_in[13];
    const float* out_W1 = (const float*)d_in[14];
    const float* out_b1 = (const float*)d_in[15];
    const float* out_W2 = (const float*)d_in[16];
    const float* out_b2 = (const float*)d_in[17];
    const int*   ei     = (const int*)d_in[18];

    const int N = NODES;
    const int E = EDGES;

    float *pp, *pbc, *pgate;
    __half *pxh, *pqh, *pHh, *pwTh;
    cudaGetSymbolAddress((void**)&pxh,   g_xh);
    cudaGetSymbolAddress((void**)&pp,    g_p);
    cudaGetSymbolAddress((void**)&pqh,   g_qh);
    cudaGetSymbolAddress((void**)&pHh,   g_Hh);
    cudaGetSymbolAddress((void**)&pwTh,  g_wTh);
    cudaGetSymbolAddress((void**)&pbc,   g_bc);
    cudaGetSymbolAddress((void**)&pgate, g_gate);

    cudaFuncSetAttribute(k_gemm_pq,    cudaFuncAttributeMaxDynamicSharedMemorySize, PQ_SMEM_BYTES);
    cudaFuncSetAttribute(k_gemm_updln, cudaFuncAttributeMaxDynamicSharedMemorySize, UPD_SMEM_BYTES);

    // CSR build
    k_init<<<(N + 255) / 256, 256>>>(ei, N);
    k_count<<<(E + 255) / 256, 256>>>(ei, E);
    k_scan1<<<(N + 1023) / 1024, 1024>>>(N);
    k_scan2<<<1, 64>>>((N + 1023) / 1024);
    k_scan3<<<(N + 255) / 256, 256>>>(N);
    k_scatter<<<(E + 255) / 256, 256>>>(ei, edge_attr, E);

    // encoder + weight prep (all layers)
    k_encode<<<(N * HID + 255) / 256, 256>>>(node_feat, enc_W, enc_b, N);
    k_repackT<<<NLAYER * 4 * 16384 / 256, 256>>>(mlp_W1, upd_W1, upd_W2);
    k_fuseW<<<dim3(128, NLAYER), 128>>>(mlp_W2, upd_W1, mlp_b2);

    const int gt64 = (N + 63) / 64;   // 782

    for (int l = 0; l < NLAYER; l++) {
        const float* W1l = mlp_W1 + (size_t)l * 257 * 128;
        __half* wl = pwTh + (size_t)l * 5 * 16384;

        // P = x @ W1a^T + b1 (fp32) ; Q = x @ W1b^T (fp16)
        k_gemm_pq<<<dim3(gt64, 2), 256, PQ_SMEM_BYTES>>>(
            pxh, wl + 0 * 16384, wl + 1 * 16384, mlp_b1 + l * 128, pp, pqh, N);

        // Hh[n] = inv_deg * sum relu(P[n] + Q[src] + ea*w1c)
        k_aggr<<<(N + 7) / 8, 256>>>(W1l + 256 * 128, N);

        // x = relu(LN( relu(x@U1a + Hh@Wc + b1 + gate*bc) @ U2 + b2 )*g + b)   [fused, in-place]
        k_gemm_updln<<<gt64, 256, UPD_SMEM_BYTES>>>(
            pxh, pHh, wl + 2 * 16384, wl + 4 * 16384, wl + 3 * 16384,
            upd_b1 + l * 128, pbc + l * 128, pgate,
            upd_b2 + l * 128, ln_g + l * 128, ln_b + l * 128, pxh, N);
    }

    // readout
    k_zero_gvec<<<1, 128>>>();
    k_mean<<<400, 128>>>(N);
    k_out<<<1, 128>>>(out_W1, out_b1, out_W2, out_b2, (float*)d_out, 1.0f / (float)N);
}

// round 9
// speedup vs baseline: 1.7738x; 1.0014x over previous
#include <cuda_runtime.h>
#include <cuda_fp16.h>
#include <cstdint>

#define NODES 50000
#define EDGES 800000
#define HID   128
#define NLAYER 3

// ---------------- scratch (static device globals; no allocation) ----------------
__device__ __half g_xh [NODES * HID];      // node state, fp16
__device__ float  g_p  [NODES * HID];      // P per node (fp32)
__device__ __half g_qh [NODES * HID];      // Q per node (fp16, gathered per edge)
__device__ __half g_Hh [NODES * HID];      // inv_deg * segment_sum(relu_h), fp16
__device__ int2  g_edge[EDGES];            // {src, ea bits}
__device__ int   g_deg [NODES];
__device__ int   g_tmp [NODES];
__device__ int   g_rowptr[NODES + 1];
__device__ int   g_cursor[NODES];
__device__ float g_invdeg[NODES];
__device__ float g_gate  [NODES];
__device__ __half g_wTh[NLAYER * 5 * HID * HID];  // B^T fp16: 0=W1a 1=W1b 2=U1a 3=U2 4=Wc
__device__ float g_bc  [NLAYER * HID];            // b2 @ U1b per layer
__device__ float g_gvec[HID];
__device__ int   g_is64;
__device__ int   g_bsum[64];

// ================= helpers =================
__device__ __forceinline__ void mma16(float* c, const uint32_t* a, const uint32_t* b) {
    asm volatile(
        "mma.sync.aligned.m16n8k16.row.col.f32.f16.f16.f32 "
        "{%0,%1,%2,%3},{%4,%5,%6,%7},{%8,%9},{%0,%1,%2,%3};"
        : "+f"(c[0]), "+f"(c[1]), "+f"(c[2]), "+f"(c[3])
        : "r"(a[0]), "r"(a[1]), "r"(a[2]), "r"(a[3]), "r"(b[0]), "r"(b[1]));
}

// ================= CSR build =================
__global__ void k_init(const int* __restrict__ ei, int N) {
    int i = blockIdx.x * blockDim.x + threadIdx.x;
    if (i < N) g_deg[i] = 0;
    if (i < 128) g_gvec[i] = 0.0f;
    if (i == 0) {
        int z = 1;
        #pragma unroll
        for (int k = 1; k < 16; k += 2) if (ei[k] != 0) z = 0;
        g_is64 = z;
    }
}
__global__ void k_count(const int* __restrict__ ei, int E) {
    int e = blockIdx.x * blockDim.x + threadIdx.x;
    if (e >= E) return;
    int is64 = g_is64;
    int dst = is64 ? ei[2 * E + 2 * e] : ei[E + e];
    atomicAdd(&g_deg[dst], 1);
}
__global__ void k_scan1(int N) {
    __shared__ int s[1024];
    int tid = threadIdx.x;
    int i = blockIdx.x * 1024 + tid;
    int v = (i < N) ? g_deg[i] : 0;
    s[tid] = v;
    __syncthreads();
    for (int off = 1; off < 1024; off <<= 1) {
        int t = (tid >= off) ? s[tid - off] : 0;
        __syncthreads();
        s[tid] += t;
        __syncthreads();
    }
    if (i < N) g_tmp[i] = s[tid];
    if (tid == 1023) g_bsum[blockIdx.x] = s[1023];
}
// scan3 with folded block-offset reduction (no scan2 kernel)
__global__ void k_scan3(int N) {
    __shared__ int sred[64];
    int tid = threadIdx.x;
    int blk = (blockIdx.x * 256) >> 10;      // which 1024-block this 256-block lies in
    if (tid < 64) sred[tid] = (tid < blk) ? g_bsum[tid] : 0;
    __syncthreads();
    #pragma unroll
    for (int off = 32; off > 0; off >>= 1) {
        if (tid < off) sred[tid] += sred[tid + off];
        __syncthreads();
    }
    int boff = sred[0];
    int i = blockIdx.x * 256 + tid;
    if (i >= N) return;
    int incl = g_tmp[i] + boff;
    int d = g_deg[i];
    int excl = incl - d;
    g_rowptr[i] = excl;
    g_cursor[i] = excl;
    g_invdeg[i] = 1.0f / fmaxf((float)d, 1.0f);
    g_gate[i]   = (d > 0) ? 1.0f : 0.0f;
    if (i == N - 1) g_rowptr[N] = incl;
}
__global__ void k_scatter(const int* __restrict__ ei, const float* __restrict__ ea, int E) {
    int e = blockIdx.x * blockDim.x + threadIdx.x;
    if (e >= E) return;
    int is64 = g_is64;
    int src = is64 ? ei[2 * e]         : ei[e];
    int dst = is64 ? ei[2 * E + 2 * e] : ei[E + e];
    int pos = atomicAdd(&g_cursor[dst], 1);
    g_edge[pos] = make_int2(src, __float_as_int(ea[e]));
}

// ================= encoder =================
__global__ void k_encode(const float* __restrict__ nf, const float* __restrict__ W,
                         const float* __restrict__ b, int N) {
    int t = blockIdx.x * blockDim.x + threadIdx.x;
    if (t >= N * HID) return;
    int n = t >> 7, c = t & 127;
    float acc = b[c];
    #pragma unroll
    for (int k = 0; k < 5; k++) acc = fmaf(nf[n * 5 + k], W[k * HID + c], acc);
    g_xh[t] = __float2half_rn(acc);
}

// ================= weight repack (ALL layers, transpose, to fp16) =================
__global__ void k_repackT(const float* __restrict__ mlp_W1, const float* __restrict__ upd_W1,
                          const float* __restrict__ upd_W2) {
    int t = blockIdx.x * blockDim.x + threadIdx.x;   // < NLAYER*4*16384
    int l = t / (4 * 16384);
    int r = t % (4 * 16384);
    int w = r >> 14;
    int j = (r >> 7) & 127;
    int k = r & 127;
    const float* W1 = mlp_W1 + (size_t)l * 257 * 128;
    const float* U1 = upd_W1 + (size_t)l * 256 * 128;
    const float* U2 = upd_W2 + (size_t)l * 128 * 128;
    float v;
    switch (w) {
        case 0:  v = W1[k * 128 + j];          break;
        case 1:  v = W1[(128 + k) * 128 + j];  break;
        case 2:  v = U1[k * 128 + j];          break;
        default: v = U2[k * 128 + j];          break;
    }
    g_wTh[(size_t)l * 5 * 16384 + (size_t)w * 16384 + j * 128 + k] = __float2half_rn(v);
}

// ================= fused small weight: Wc = W2 @ U1b, bc = b2 @ U1b =================
__global__ void k_fuseW(const float* __restrict__ mlp_W2, const float* __restrict__ upd_W1,
                        const float* __restrict__ mlp_b2) {
    __shared__ float w2row[128];
    int k = blockIdx.x, l = blockIdx.y, j = threadIdx.x;
    const float* W2 = mlp_W2 + (size_t)l * 128 * 128;
    const float* U1 = upd_W1 + (size_t)l * 256 * 128;
    const float* b2 = mlp_b2 + l * 128;
    w2row[j] = W2[k * 128 + j];
    __syncthreads();
    float acc = 0.f;
    #pragma unroll 8
    for (int t = 0; t < 128; t++) acc = fmaf(w2row[t], U1[(128 + t) * 128 + j], acc);
    g_wTh[(size_t)l * 5 * 16384 + 4 * 16384 + j * 128 + k] = __float2half_rn(acc);
    if (k == 0) {
        float bacc = 0.f;
        #pragma unroll 8
        for (int t = 0; t < 128; t++) bacc = fmaf(b2[t], U1[(128 + t) * 128 + j], bacc);
        g_bc[l * 128 + j] = bacc;
    }
}

// ================= fp16 mma.sync GEMMs: 64x128 CTA tile, 8 warps (2m x 4n) =================
#define STR  72
#define STRT 136
#define PQ_SMEM_BYTES   ((64 + 128) * STR * 2)
#define UPD_SMEM_BYTES  (((64 + 128) * STR + 64 * STRT) * 2)

// ---- layer-0 PQ kernel: y=0 -> P = x@W1a^T + b1 (fp32); y=1 -> Q = x@W1b^T (fp16) ----
__global__ void __launch_bounds__(256, 3)
k_gemm_pq(const __half* __restrict__ A1,
          const __half* __restrict__ B1, const __half* __restrict__ B2,
          const float* __restrict__ bias,
          float* __restrict__ Cf, __half* __restrict__ Ch, int M)
{
    extern __shared__ __half smh[];
    __half* As = smh;
    __half* Bs = smh + 64 * STR;

    const int tid = threadIdx.x;
    const int wid = tid >> 5, lane = tid & 31;
    const int g = lane >> 2, tig = lane & 3;
    const int warp_m = wid >> 2, warp_n = wid & 3;
    const int mw = warp_m * 32, nw = warp_n * 32;
    const int m0 = blockIdx.x * 64;
    const __half* B = (blockIdx.y == 0) ? B1 : B2;

    float acc[2][4][4];
    #pragma unroll
    for (int i = 0; i < 2; i++)
        #pragma unroll
        for (int j = 0; j < 4; j++)
            #pragma unroll
            for (int r = 0; r < 4; r++) acc[i][j][r] = 0.0f;

    for (int c = 0; c < 2; c++) {
        __syncthreads();
        #pragma unroll
        for (int u = 0; u < 2; u++) {
            int linear = u * 256 + tid;
            int row = linear >> 3, q = linear & 7;
            uint4 av = make_uint4(0u, 0u, 0u, 0u);
            if (m0 + row < M)
                av = *(const uint4*)&A1[(size_t)(m0 + row) * 128 + c * 64 + q * 8];
            *(uint4*)&As[row * STR + q * 8] = av;
        }
        #pragma unroll
        for (int u = 0; u < 4; u++) {
            int linear = u * 256 + tid;
            int row = linear >> 3, q = linear & 7;
            *(uint4*)&Bs[row * STR + q * 8] =
                *(const uint4*)&B[(size_t)row * 128 + c * 64 + q * 8];
        }
        __syncthreads();
        #pragma unroll
        for (int ks = 0; ks < 4; ks++) {
            const int k0 = ks * 16;
            uint32_t af[2][4], bf[4][2];
            #pragma unroll
            for (int i = 0; i < 2; i++) {
                const __half* r0 = &As[(mw + i * 16 + g) * STR + k0 + 2 * tig];
                const __half* r1 = r0 + 8 * STR;
                af[i][0] = *(const uint32_t*)r0;
                af[i][1] = *(const uint32_t*)r1;
                af[i][2] = *(const uint32_t*)(r0 + 8);
                af[i][3] = *(const uint32_t*)(r1 + 8);
            }
            #pragma unroll
            for (int j = 0; j < 4; j++) {
                const __half* rb = &Bs[(nw + j * 8 + g) * STR + k0 + 2 * tig];
                bf[j][0] = *(const uint32_t*)rb;
                bf[j][1] = *(const uint32_t*)(rb + 8);
            }
            #pragma unroll
            for (int i = 0; i < 2; i++)
                #pragma unroll
                for (int j = 0; j < 4; j++)
                    mma16(acc[i][j], af[i], bf[j]);
        }
    }

    float bcol[4][2];
    #pragma unroll
    for (int j = 0; j < 4; j++) {
        int col = nw + j * 8 + 2 * tig;
        bool haveb = (blockIdx.y == 0);
        bcol[j][0] = haveb ? bias[col]     : 0.0f;
        bcol[j][1] = haveb ? bias[col + 1] : 0.0f;
    }
    #pragma unroll
    for (int i = 0; i < 2; i++) {
        #pragma unroll
        for (int h = 0; h < 2; h++) {
            int row = m0 + mw + i * 16 + g + 8 * h;
            if (row >= M) continue;
            #pragma unroll
            for (int j = 0; j < 4; j++) {
                int col = nw + j * 8 + 2 * tig;
                float v0 = acc[i][j][2 * h] + bcol[j][0];
                float v1 = acc[i][j][2 * h + 1] + bcol[j][1];
                if (blockIdx.y == 0) {
                    float2 o; o.x = v0; o.y = v1;
                    *(float2*)&Cf[(size_t)row * 128 + col] = o;
                } else {
                    *(__half2*)&Ch[(size_t)row * 128 + col] = __floats2half2_rn(v0, v1);
                }
            }
        }
    }
}

// ---- fused UPD + LN (+ next-layer PQ, or readout mean) ----
// phase 1: t = relu(x@U1a + Hh@Wc + b1 + gate*bc)  -> smem T
// phase 2: x = relu(LN(t@U2 + b2)*lng + lnb)       -> g_xh (TAIL!=2) and smem T (TAIL==1)
// TAIL==1: P = x@W1a'^T + bP (fp32), Q = x@W1b'^T (fp16) from smem T
// TAIL==2: column sums of x accumulated into g_gvec (x not written to gmem)
template<int TAIL>
__global__ void __launch_bounds__(256, 3)
k_updln(const __half* __restrict__ A1, const __half* __restrict__ A2,
        const __half* __restrict__ B1, const __half* __restrict__ B2,
        const __half* __restrict__ B3,
        const __half* __restrict__ B4, const __half* __restrict__ B5,
        const float* __restrict__ bias, const float* __restrict__ bias2,
        const float* __restrict__ rowgate,
        const float* __restrict__ biasln,
        const float* __restrict__ lng, const float* __restrict__ lnb,
        const float* __restrict__ bP,
        __half* __restrict__ Ch, float* __restrict__ Pf, __half* __restrict__ Qh, int M)
{
    extern __shared__ __half smh[];
    __half* As = smh;                        // [64][72]
    __half* Bs = smh + 64 * STR;             // [128][72]
    __half* T  = smh + (64 + 128) * STR;     // [64][136]

    const int tid = threadIdx.x;
    const int wid = tid >> 5, lane = tid & 31;
    const int g = lane >> 2, tig = lane & 3;
    const int warp_m = wid >> 2, warp_n = wid & 3;
    const int mw = warp_m * 32, nw = warp_n * 32;
    const int m0 = blockIdx.x * 64;

    float acc[2][4][4];
    #pragma unroll
    for (int i = 0; i < 2; i++)
        #pragma unroll
        for (int j = 0; j < 4; j++)
            #pragma unroll
            for (int r = 0; r < 4; r++) acc[i][j][r] = 0.0f;

    // ---- phase 1: dual-input GEMM ----
    for (int p = 0; p < 2; p++) {
        const __half* A = p ? A2 : A1;
        const __half* B = p ? B2 : B1;
        for (int c = 0; c < 2; c++) {
            __syncthreads();
            #pragma unroll
            for (int u = 0; u < 2; u++) {
                int linear = u * 256 + tid;
                int row = linear >> 3, q = linear & 7;
                uint4 av = make_uint4(0u, 0u, 0u, 0u);
                if (m0 + row < M)
                    av = *(const uint4*)&A[(size_t)(m0 + row) * 128 + c * 64 + q * 8];
                *(uint4*)&As[row * STR + q * 8] = av;
            }
            #pragma unroll
            for (int u = 0; u < 4; u++) {
                int linear = u * 256 + tid;
                int row = linear >> 3, q = linear & 7;
                *(uint4*)&Bs[row * STR + q * 8] =
                    *(const uint4*)&B[(size_t)row * 128 + c * 64 + q * 8];
            }
            __syncthreads();
            #pragma unroll
            for (int ks = 0; ks < 4; ks++) {
                const int k0 = ks * 16;
                uint32_t af[2][4], bf[4][2];
                #pragma unroll
                for (int i = 0; i < 2; i++) {
                    const __half* r0 = &As[(mw + i * 16 + g) * STR + k0 + 2 * tig];
                    const __half* r1 = r0 + 8 * STR;
                    af[i][0] = *(const uint32_t*)r0;
                    af[i][1] = *(const uint32_t*)r1;
                    af[i][2] = *(const uint32_t*)(r0 + 8);
                    af[i][3] = *(const uint32_t*)(r1 + 8);
                }
                #pragma unroll
                for (int j = 0; j < 4; j++) {
                    const __half* rb = &Bs[(nw + j * 8 + g) * STR + k0 + 2 * tig];
                    bf[j][0] = *(const uint32_t*)rb;
                    bf[j][1] = *(const uint32_t*)(rb + 8);
                }
                #pragma unroll
                for (int i = 0; i < 2; i++)
                    #pragma unroll
                    for (int j = 0; j < 4; j++)
                        mma16(acc[i][j], af[i], bf[j]);
            }
        }
    }

    // ---- epilogue 1: t -> smem T ----
    {
        float bcol[4][2], b2col[4][2];
        #pragma unroll
        for (int j = 0; j < 4; j++) {
            int col = nw + j * 8 + 2 * tig;
            bcol[j][0]  = bias[col];      bcol[j][1]  = bias[col + 1];
            b2col[j][0] = bias2[col];     b2col[j][1] = bias2[col + 1];
        }
        #pragma unroll
        for (int i = 0; i < 2; i++) {
            #pragma unroll
            for (int h = 0; h < 2; h++) {
                int rl = mw + i * 16 + g + 8 * h;
                int row = m0 + rl;
                float gt = (row < M) ? rowgate[row] : 0.f;
                #pragma unroll
                for (int j = 0; j < 4; j++) {
                    int col = nw + j * 8 + 2 * tig;
                    float v0 = fmaxf(acc[i][j][2*h]   + bcol[j][0] + gt * b2col[j][0], 0.f);
                    float v1 = fmaxf(acc[i][j][2*h+1] + bcol[j][1] + gt * b2col[j][1], 0.f);
                    *(__half2*)&T[rl * STRT + col] = __floats2half2_rn(v0, v1);
                }
            }
        }
    }
    #pragma unroll
    for (int i = 0; i < 2; i++)
        #pragma unroll
        for (int j = 0; j < 4; j++)
            #pragma unroll
            for (int r = 0; r < 4; r++) acc[i][j][r] = 0.0f;

    // ---- phase 2: t @ U2^T ----
    for (int c = 0; c < 2; c++) {
        __syncthreads();
        #pragma unroll
        for (int u = 0; u < 4; u++) {
            int linear = u * 256 + tid;
            int row = linear >> 3, q = linear & 7;
            *(uint4*)&Bs[row * STR + q * 8] =
                *(const uint4*)&B3[(size_t)row * 128 + c * 64 + q * 8];
        }
        __syncthreads();
        #pragma unroll
        for (int ks = 0; ks < 4; ks++) {
            const int k0 = c * 64 + ks * 16;
            uint32_t af[2][4], bf[4][2];
            #pragma unroll
            for (int i = 0; i < 2; i++) {
                const __half* r0 = &T[(mw + i * 16 + g) * STRT + k0 + 2 * tig];
                const __half* r1 = r0 + 8 * STRT;
                af[i][0] = *(const uint32_t*)r0;
                af[i][1] = *(const uint32_t*)r1;
                af[i][2] = *(const uint32_t*)(r0 + 8);
                af[i][3] = *(const uint32_t*)(r1 + 8);
            }
            #pragma unroll
            for (int j = 0; j < 4; j++) {
                const __half* rb = &Bs[(nw + j * 8 + g) * STR + (ks * 16) + 2 * tig];
                bf[j][0] = *(const uint32_t*)rb;
                bf[j][1] = *(const uint32_t*)(rb + 8);
            }
            #pragma unroll
            for (int i = 0; i < 2; i++)
                #pragma unroll
                for (int j = 0; j < 4; j++)
                    mma16(acc[i][j], af[i], bf[j]);
        }
    }

    // ---- LN epilogue (x -> gmem / smem T / gvec) ----
    float csum[4][2];
    #pragma unroll
    for (int j = 0; j < 4; j++) { csum[j][0] = 0.f; csum[j][1] = 0.f; }
    {
        __syncthreads();
        float* sS  = (float*)As;            // [64][4]
        float* sS2 = (float*)As + 256;
        float bcol[4][2], gcol[4][2], lcol[4][2];
        #pragma unroll
        for (int j = 0; j < 4; j++) {
            int col = nw + j * 8 + 2 * tig;
            bcol[j][0] = biasln[col];  bcol[j][1] = biasln[col + 1];
            gcol[j][0] = lng[col];     gcol[j][1] = lng[col + 1];
            lcol[j][0] = lnb[col];     lcol[j][1] = lnb[col + 1];
        }
        #pragma unroll
        for (int i = 0; i < 2; i++) {
            #pragma unroll
            for (int h = 0; h < 2; h++) {
                float s = 0.f, s2 = 0.f;
                #pragma unroll
                for (int j = 0; j < 4; j++) {
                    #pragma unroll
                    for (int r = 0; r < 2; r++) {
                        float v = acc[i][j][2 * h + r] + bcol[j][r];
                        s += v; s2 += v * v;
                    }
                }
                s  += __shfl_xor_sync(0xffffffffu, s, 1);
                s  += __shfl_xor_sync(0xffffffffu, s, 2);
                s2 += __shfl_xor_sync(0xffffffffu, s2, 1);
                s2 += __shfl_xor_sync(0xffffffffu, s2, 2);
                if (tig == 0) {
                    int rl = mw + i * 16 + g + 8 * h;
                    sS [rl * 4 + warp_n] = s;
                    sS2[rl * 4 + warp_n] = s2;
                }
            }
        }
        __syncthreads();
        #pragma unroll
        for (int i = 0; i < 2; i++) {
            #pragma unroll
            for (int h = 0; h < 2; h++) {
                int rl = mw + i * 16 + g + 8 * h;
                int row = m0 + rl;
                float s  = sS [rl * 4] + sS [rl * 4 + 1] + sS [rl * 4 + 2] + sS [rl * 4 + 3];
                float s2 = sS2[rl * 4] + sS2[rl * 4 + 1] + sS2[rl * 4 + 2] + sS2[rl * 4 + 3];
                float mu   = s * (1.0f / 128.0f);
                float var  = s2 * (1.0f / 128.0f) - mu * mu;
                float rstd = rsqrtf(var + 1e-5f);
                #pragma unroll
                for (int j = 0; j < 4; j++) {
                    int col = nw + j * 8 + 2 * tig;
                    float v0 = fmaxf((acc[i][j][2*h]   + bcol[j][0] - mu) * rstd * gcol[j][0] + lcol[j][0], 0.f);
                    float v1 = fmaxf((acc[i][j][2*h+1] + bcol[j][1] - mu) * rstd * gcol[j][1] + lcol[j][1], 0.f);
                    __half2 hv = __floats2half2_rn(v0, v1);
                    if constexpr (TAIL == 1) *(__half2*)&T[rl * STRT + col] = hv;
                    if (row < M) {
                        if constexpr (TAIL != 2) *(__half2*)&Ch[(size_t)row * 128 + col] = hv;
                        if constexpr (TAIL == 2) { csum[j][0] += v0; csum[j][1] += v1; }
                    }
                }
            }
        }
    }

    if constexpr (TAIL == 2) {
        // stage column sums in smem, then 128 global atomics
        __syncthreads();
        float* sgv = (float*)Bs;
        if (tid < 128) sgv[tid] = 0.f;
        __syncthreads();
        #pragma unroll
        for (int j = 0; j < 4; j++) {
            int col = nw + j * 8 + 2 * tig;
            atomicAdd(&sgv[col],     csum[j][0]);
            atomicAdd(&sgv[col + 1], csum[j][1]);
        }
        __syncthreads();
        if (tid < 128) atomicAdd(&g_gvec[tid], sgv[tid]);
    }

    if constexpr (TAIL == 1) {
        __syncthreads();   // T (new x) visible to all
        // two GEMM passes from T: P = x@W1a'^T + bP (fp32), Q = x@W1b'^T (fp16)
        #pragma unroll
        for (int pq = 0; pq < 2; pq++) {
            const __half* B = pq ? B5 : B4;
            #pragma unroll
            for (int i = 0; i < 2; i++)
                #pragma unroll
                for (int j = 0; j < 4; j++)
                    #pragma unroll
                    for (int r = 0; r < 4; r++) acc[i][j][r] = 0.0f;
            for (int c = 0; c < 2; c++) {
                __syncthreads();
                #pragma unroll
                for (int u = 0; u < 4; u++) {
                    int linear = u * 256 + tid;
                    int row = linear >> 3, q = linear & 7;
                    *(uint4*)&Bs[row * STR + q * 8] =
                        *(const uint4*)&B[(size_t)row * 128 + c * 64 + q * 8];
                }
                __syncthreads();
                #pragma unroll
                for (int ks = 0; ks < 4; ks++) {
                    const int k0 = c * 64 + ks * 16;
                    uint32_t af[2][4], bf[4][2];
                    #pragma unroll
                    for (int i = 0; i < 2; i++) {
                        const __half* r0 = &T[(mw + i * 16 + g) * STRT + k0 + 2 * tig];
                        const __half* r1 = r0 + 8 * STRT;
                        af[i][0] = *(const uint32_t*)r0;
                        af[i][1] = *(const uint32_t*)r1;
                        af[i][2] = *(const uint32_t*)(r0 + 8);
                        af[i][3] = *(const uint32_t*)(r1 + 8);
                    }
                    #pragma unroll
                    for (int j = 0; j < 4; j++) {
                        const __half* rb = &Bs[(nw + j * 8 + g) * STR + (ks * 16) + 2 * tig];
                        bf[j][0] = *(const uint32_t*)rb;
                        bf[j][1] = *(const uint32_t*)(rb + 8);
                    }
                    #pragma unroll
                    for (int i = 0; i < 2; i++)
                        #pragma unroll
                        for (int j = 0; j < 4; j++)
                            mma16(acc[i][j], af[i], bf[j]);
                }
            }
            if (pq == 0) {
                float bq[4][2];
                #pragma unroll
                for (int j = 0; j < 4; j++) {
                    int col = nw + j * 8 + 2 * tig;
                    bq[j][0] = bP[col]; bq[j][1] = bP[col + 1];
                }
                #pragma unroll
                for (int i = 0; i < 2; i++) {
                    #pragma unroll
                    for (int h = 0; h < 2; h++) {
                        int row = m0 + mw + i * 16 + g + 8 * h;
                        if (row >= M) continue;
                        #pragma unroll
                        for (int j = 0; j < 4; j++) {
                            int col = nw + j * 8 + 2 * tig;
                            float2 o;
                            o.x = acc[i][j][2 * h]     + bq[j][0];
                            o.y = acc[i][j][2 * h + 1] + bq[j][1];
                            *(float2*)&Pf[(size_t)row * 128 + col] = o;
                        }
                    }
                }
            } else {
                #pragma unroll
                for (int i = 0; i < 2; i++) {
                    #pragma unroll
                    for (int h = 0; h < 2; h++) {
                        int row = m0 + mw + i * 16 + g + 8 * h;
                        if (row >= M) continue;
                        #pragma unroll
                        for (int j = 0; j < 4; j++) {
                            int col = nw + j * 8 + 2 * tig;
                            *(__half2*)&Qh[(size_t)row * 128 + col] =
                                __floats2half2_rn(acc[i][j][2 * h], acc[i][j][2 * h + 1]);
                        }
                    }
                }
            }
        }
    }
}

// ================= edge aggregation: warp per node, fp16 Q gather, 4x unroll =================
__global__ void __launch_bounds__(256) k_aggr(const float* __restrict__ w1c, int N) {
    int warp = (blockIdx.x * blockDim.x + threadIdx.x) >> 5;
    int lane = threadIdx.x & 31;
    if (warp >= N) return;
    int node = warp;
    float4 p = *(const float4*)&g_p[(size_t)node * 128 + lane * 4];
    float4 w = *(const float4*)&w1c[lane * 4];
    float4 acc = make_float4(0.f, 0.f, 0.f, 0.f);
    int s0 = g_rowptr[node], s1 = g_rowptr[node + 1];
    const int2* ep = g_edge;
    int j = s0;
    for (; j + 3 < s1; j += 4) {
        int2 e0 = __ldg(&ep[j]);
        int2 e1 = __ldg(&ep[j + 1]);
        int2 e2 = __ldg(&ep[j + 2]);
        int2 e3 = __ldg(&ep[j + 3]);
        uint2 r0 = *(const uint2*)&g_qh[(size_t)e0.x * 128 + lane * 4];
        uint2 r1 = *(const uint2*)&g_qh[(size_t)e1.x * 128 + lane * 4];
        uint2 r2 = *(const uint2*)&g_qh[(size_t)e2.x * 128 + lane * 4];
        uint2 r3 = *(const uint2*)&g_qh[(size_t)e3.x * 128 + lane * 4];
        float ea0 = __int_as_float(e0.y), ea1 = __int_as_float(e1.y);
        float ea2 = __int_as_float(e2.y), ea3 = __int_as_float(e3.y);
        float2 a0 = __half22float2(*(const __half2*)&r0.x);
        float2 a1 = __half22float2(*(const __half2*)&r0.y);
        float2 b0 = __half22float2(*(const __half2*)&r1.x);
        float2 b1 = __half22float2(*(const __half2*)&r1.y);
        float2 c0 = __half22float2(*(const __half2*)&r2.x);
        float2 c1 = __half22float2(*(const __half2*)&r2.y);
        float2 d0 = __half22float2(*(const __half2*)&r3.x);
        float2 d1 = __half22float2(*(const __half2*)&r3.y);
        acc.x += fmaxf(fmaf(ea0, w.x, p.x + a0.x), 0.f) + fmaxf(fmaf(ea1, w.x, p.x + b0.x), 0.f)
               + fmaxf(fmaf(ea2, w.x, p.x + c0.x), 0.f) + fmaxf(fmaf(ea3, w.x, p.x + d0.x), 0.f);
        acc.y += fmaxf(fmaf(ea0, w.y, p.y + a0.y), 0.f) + fmaxf(fmaf(ea1, w.y, p.y + b0.y), 0.f)
               + fmaxf(fmaf(ea2, w.y, p.y + c0.y), 0.f) + fmaxf(fmaf(ea3, w.y, p.y + d0.y), 0.f);
        acc.z += fmaxf(fmaf(ea0, w.z, p.z + a1.x), 0.f) + fmaxf(fmaf(ea1, w.z, p.z + b1.x), 0.f)
               + fmaxf(fmaf(ea2, w.z, p.z + c1.x), 0.f) + fmaxf(fmaf(ea3, w.z, p.z + d1.x), 0.f);
        acc.w += fmaxf(fmaf(ea0, w.w, p.w + a1.y), 0.f) + fmaxf(fmaf(ea1, w.w, p.w + b1.y), 0.f)
               + fmaxf(fmaf(ea2, w.w, p.w + c1.y), 0.f) + fmaxf(fmaf(ea3, w.w, p.w + d1.y), 0.f);
    }
    for (; j < s1; j++) {
        int2 e = __ldg(&ep[j]);
        float ea = __int_as_float(e.y);
        uint2 ra = *(const uint2*)&g_qh[(size_t)e.x * 128 + lane * 4];
        float2 a0 = __half22float2(*(const __half2*)&ra.x);
        float2 a1 = __half22float2(*(const __half2*)&ra.y);
        acc.x += fmaxf(fmaf(ea, w.x, p.x + a0.x), 0.f);
        acc.y += fmaxf(fmaf(ea, w.y, p.y + a0.y), 0.f);
        acc.z += fmaxf(fmaf(ea, w.z, p.z + a1.x), 0.f);
        acc.w += fmaxf(fmaf(ea, w.w, p.w + a1.y), 0.f);
    }
    float inv = g_invdeg[node];
    __half2 h0 = __floats2half2_rn(acc.x * inv, acc.y * inv);
    __half2 h1 = __floats2half2_rn(acc.z * inv, acc.w * inv);
    uint2 u; u.x = *(uint32_t*)&h0; u.y = *(uint32_t*)&h1;
    *(uint2*)&g_Hh[(size_t)node * 128 + lane * 4] = u;
}

// ================= readout =================
__global__ void k_out(const float* __restrict__ W1, const float* __restrict__ b1,
                      const float* __restrict__ W2, const float* __restrict__ b2,
                      float* __restrict__ out, float invN) {
    __shared__ float gs[128];
    __shared__ float hs[128];
    int c = threadIdx.x;
    gs[c] = g_gvec[c] * invN;
    __syncthreads();
    float a = b1[c];
    #pragma unroll 8
    for (int k = 0; k < 128; k++) a = fmaf(gs[k], W1[k * 128 + c], a);
    hs[c] = fmaxf(a, 0.0f);
    __syncthreads();
    float o = b2[c];
    #pragma unroll 8
    for (int k = 0; k < 128; k++) o = fmaf(hs[k], W2[k * 128 + c], o);
    out[c] = o;
}

// ================= launch =================
extern "C" void kernel_launch(void* const* d_in, const int* in_sizes, int n_in,
                              void* d_out, int out_size) {
    const float* node_feat = (const float*)d_in[0];
    const float* edge_attr = (const float*)d_in[1];
    const float* enc_W  = (const float*)d_in[2];
    const float* enc_b  = (const float*)d_in[3];
    const float* mlp_W1 = (const float*)d_in[4];
    const float* mlp_b1 = (const float*)d_in[5];
    const float* mlp_W2 = (const float*)d_in[6];
    const float* mlp_b2 = (const float*)d_in[7];
    const float* upd_W1 = (const float*)d_in[8];
    const float* upd_b1 = (const float*)d_in[9];
    const float* upd_W2 = (const float*)d_in[10];
    const float* upd_b2 = (const float*)d_in[11];
    const float* ln_g   = (const float*)d_in[12];
    const float* ln_b   = (const float*)d_in[13];
    const float* out_W1 = (const float*)d_in[14];
    const float* out_b1 = (const float*)d_in[15];
    const float* out_W2 = (const float*)d_in[16];
    const float* out_b2 = (const float*)d_in[17];
    const int*   ei     = (const int*)d_in[18];

    const int N = NODES;
    const int E = EDGES;

    float *pp, *pbc, *pgate;
    __half *pxh, *pqh, *pHh, *pwTh;
    cudaGetSymbolAddress((void**)&pxh,   g_xh);
    cudaGetSymbolAddress((void**)&pp,    g_p);
    cudaGetSymbolAddress((void**)&pqh,   g_qh);
    cudaGetSymbolAddress((void**)&pHh,   g_Hh);
    cudaGetSymbolAddress((void**)&pwTh,  g_wTh);
    cudaGetSymbolAddress((void**)&pbc,   g_bc);
    cudaGetSymbolAddress((void**)&pgate, g_gate);

    cudaFuncSetAttribute(k_gemm_pq, cudaFuncAttributeMaxDynamicSharedMemorySize, PQ_SMEM_BYTES);
    cudaFuncSetAttribute(k_updln<1>, cudaFuncAttributeMaxDynamicSharedMemorySize, UPD_SMEM_BYTES);
    cudaFuncSetAttribute(k_updln<2>, cudaFuncAttributeMaxDynamicSharedMemorySize, UPD_SMEM_BYTES);

    // CSR build (scan2 folded into scan3; gvec zeroed in init)
    k_init<<<(N + 255) / 256, 256>>>(ei, N);
    k_count<<<(E + 255) / 256, 256>>>(ei, E);
    k_scan1<<<(N + 1023) / 1024, 1024>>>(N);
    k_scan3<<<(N + 255) / 256, 256>>>(N);
    k_scatter<<<(E + 255) / 256, 256>>>(ei, edge_attr, E);

    // encoder + weight prep (all layers)
    k_encode<<<(N * HID + 255) / 256, 256>>>(node_feat, enc_W, enc_b, N);
    k_repackT<<<NLAYER * 4 * 16384 / 256, 256>>>(mlp_W1, upd_W1, upd_W2);
    k_fuseW<<<dim3(128, NLAYER), 128>>>(mlp_W2, upd_W1, mlp_b2);

    const int gt64 = (N + 63) / 64;   // 782

    // layer 0 PQ (from encoder x)
    k_gemm_pq<<<dim3(gt64, 2), 256, PQ_SMEM_BYTES>>>(
        pxh, pwTh + 0 * 16384, pwTh + 1 * 16384, mlp_b1, pp, pqh, N);

    for (int l = 0; l < NLAYER; l++) {
        const float* W1l = mlp_W1 + (size_t)l * 257 * 128;
        __half* wl = pwTh + (size_t)l * 5 * 16384;

        // Hh[n] = inv_deg * sum relu(P[n] + Q[src] + ea*w1c)
        k_aggr<<<(N + 7) / 8, 256>>>(W1l + 256 * 128, N);

        if (l < NLAYER - 1) {
            __half* wn = pwTh + (size_t)(l + 1) * 5 * 16384;
            // x' = relu(LN(relu(x@U1a + Hh@Wc + b1 + gate*bc) @ U2 + b2)) ; P,Q for next layer
            k_updln<1><<<gt64, 256, UPD_SMEM_BYTES>>>(
                pxh, pHh, wl + 2 * 16384, wl + 4 * 16384, wl + 3 * 16384,
                wn + 0 * 16384, wn + 1 * 16384,
                upd_b1 + l * 128, pbc + l * 128, pgate,
                upd_b2 + l * 128, ln_g + l * 128, ln_b + l * 128,
                mlp_b1 + (l + 1) * 128,
                pxh, pp, pqh, N);
        } else {
            // final layer: fused column-mean into g_gvec; x not written to gmem
            k_updln<2><<<gt64, 256, UPD_SMEM_BYTES>>>(
                pxh, pHh, wl + 2 * 16384, wl + 4 * 16384, wl + 3 * 16384,
                nullptr, nullptr,
                upd_b1 + l * 128, pbc + l * 128, pgate,
                upd_b2 + l * 128, ln_g + l * 128, ln_b + l * 128,
                nullptr,
                pxh, pp, pqh, N);
        }
    }

    // readout
    k_out<<<1, 128>>>(out_W1, out_b1, out_W2, out_b2, (float*)d_out, 1.0f / (float)N);
}